// round 4
// baseline (speedup 1.0000x reference)
#include <cuda_runtime.h>
#include <math.h>

#define NUM_USERS 162541
#define NUM_ITEMS 59047
#define N_NODES   221588
#define DIM       128
#define N_EDGES   100000
#define BATCH     16384

// ---------------- scratch (device globals; no allocations allowed) ----------
// Referenced ONLY from device code (host passing of __device__ symbols is the
// bug that sank rounds 2-3: host shadow address -> HMM page migration).
__device__ float g_xw [N_NODES * DIM];   // x @ W        [N,128]
__device__ float g_out[N_NODES * DIM];   // aggregation  [N,128]
__device__ float g_asrc [N_NODES * 4];
__device__ float g_adst [N_NODES * 4];
__device__ float g_denom[N_NODES * 4];

// ---------------- helpers ---------------------------------------------------
__device__ __forceinline__ float eluf(float x)   { return x > 0.f ? x : expm1f(x); }
__device__ __forceinline__ float lrelu(float x)  { return x > 0.f ? x : 0.2f * x; }
__device__ __forceinline__ float wsum(float v) {
    #pragma unroll
    for (int o = 16; o; o >>= 1) v += __shfl_xor_sync(0xffffffffu, v, o);
    return v;
}

// ---------------- GEMM: g_xw[M,128] = A[M,128] @ W[128,128] -----------------
// MODE 0: A row r = (r < NUM_USERS ? user_table[r] : item_table[r-NUM_USERS])
// MODE 1: A row r = elu(g_out[r] + biasPrev)
#define BM 128
#define BN 128
#define BK 16
#define ASTR 132   // padded stride to kill store conflicts

template<int MODE>
__global__ __launch_bounds__(256, 1)
void gemm_k(const float* __restrict__ userT, const float* __restrict__ itemT,
            const float* __restrict__ biasPrev, const float* __restrict__ W)
{
    __shared__ float As[BK][ASTR];
    __shared__ float Bs[BK][BN];

    const int tid  = threadIdx.x;
    const int row0 = blockIdx.x * BM;
    const int tx   = tid & 15;      // col group (8 cols each)
    const int ty   = tid >> 4;      // row group (8 rows each)

    float acc[8][8];
    #pragma unroll
    for (int i = 0; i < 8; i++)
        #pragma unroll
        for (int j = 0; j < 8; j++) acc[i][j] = 0.f;

    for (int kk = 0; kk < DIM; kk += BK) {
        #pragma unroll
        for (int it = 0; it < 2; it++) {
            int f  = tid + it * 256;
            // ---- A tile: 128 rows x 16 cols, transposed into As[k][row] ----
            int r  = f >> 2;
            int c4 = (f & 3) * 4;
            int gr = row0 + r;
            float4 v = make_float4(0.f, 0.f, 0.f, 0.f);
            if (gr < N_NODES) {
                if (MODE == 0) {
                    const float* p = (gr < NUM_USERS)
                        ? (userT + (size_t)gr * DIM)
                        : (itemT + (size_t)(gr - NUM_USERS) * DIM);
                    v = *(const float4*)(p + kk + c4);
                } else {
                    v = *(const float4*)(g_out + (size_t)gr * DIM + kk + c4);
                    float4 bb = *(const float4*)(biasPrev + kk + c4);
                    v.x = eluf(v.x + bb.x); v.y = eluf(v.y + bb.y);
                    v.z = eluf(v.z + bb.z); v.w = eluf(v.w + bb.w);
                }
            }
            As[c4 + 0][r] = v.x; As[c4 + 1][r] = v.y;
            As[c4 + 2][r] = v.z; As[c4 + 3][r] = v.w;
            // ---- B tile: 16 rows x 128 cols ----
            int kr = f >> 5;
            int bc = (f & 31) * 4;
            *(float4*)&Bs[kr][bc] = *(const float4*)(W + (size_t)(kk + kr) * DIM + bc);
        }
        __syncthreads();

        #pragma unroll
        for (int k = 0; k < BK; k++) {
            // Shared->register via float4 VALUES; spread with brace-init so
            // no thread-local object's address is ever taken (no local mem).
            float4 a0 = *(const float4*)&As[k][ty * 8];
            float4 a1 = *(const float4*)&As[k][ty * 8 + 4];
            float4 b0 = *(const float4*)&Bs[k][tx * 8];
            float4 b1 = *(const float4*)&Bs[k][tx * 8 + 4];
            float a[8] = {a0.x, a0.y, a0.z, a0.w, a1.x, a1.y, a1.z, a1.w};
            float b[8] = {b0.x, b0.y, b0.z, b0.w, b1.x, b1.y, b1.z, b1.w};
            #pragma unroll
            for (int i = 0; i < 8; i++)
                #pragma unroll
                for (int j = 0; j < 8; j++)
                    acc[i][j] = fmaf(a[i], b[j], acc[i][j]);
        }
        __syncthreads();
    }

    #pragma unroll
    for (int i = 0; i < 8; i++) {
        int gr = row0 + ty * 8 + i;
        if (gr < N_NODES) {
            float* o = g_xw + (size_t)gr * DIM + tx * 8;   // device symbol, device code
            *(float4*)(o)     = make_float4(acc[i][0], acc[i][1], acc[i][2], acc[i][3]);
            *(float4*)(o + 4) = make_float4(acc[i][4], acc[i][5], acc[i][6], acc[i][7]);
        }
    }
}

// ---------------- per-node attention scores + self-loop denom init ----------
// warp per node; lane l covers channels {l, l+32, l+64, l+96}
template<int H>
__global__ __launch_bounds__(256, 1)
void scores_k(const float* __restrict__ attS, const float* __restrict__ attD)
{
    int gw   = (blockIdx.x * blockDim.x + threadIdx.x) >> 5;
    int lane = threadIdx.x & 31;
    if (gw >= N_NODES) return;
    const float* xr = g_xw + (size_t)gw * DIM;
    float v0 = xr[lane];      float v1 = xr[lane + 32];
    float v2 = xr[lane + 64]; float v3 = xr[lane + 96];
    float ps0 = v0 * attS[lane];      float pd0 = v0 * attD[lane];
    float ps1 = v1 * attS[lane + 32]; float pd1 = v1 * attD[lane + 32];
    float ps2 = v2 * attS[lane + 64]; float pd2 = v2 * attD[lane + 64];
    float ps3 = v3 * attS[lane + 96]; float pd3 = v3 * attD[lane + 96];
    if (H == 4) {
        ps0 = wsum(ps0); ps1 = wsum(ps1); ps2 = wsum(ps2); ps3 = wsum(ps3);
        pd0 = wsum(pd0); pd1 = wsum(pd1); pd2 = wsum(pd2); pd3 = wsum(pd3);
        if (lane == 0) {
            g_asrc[gw * 4 + 0] = ps0; g_adst[gw * 4 + 0] = pd0;
            g_asrc[gw * 4 + 1] = ps1; g_adst[gw * 4 + 1] = pd1;
            g_asrc[gw * 4 + 2] = ps2; g_adst[gw * 4 + 2] = pd2;
            g_asrc[gw * 4 + 3] = ps3; g_adst[gw * 4 + 3] = pd3;
            g_denom[gw * 4 + 0] = expf(lrelu(ps0 + pd0));   // self loop term
            g_denom[gw * 4 + 1] = expf(lrelu(ps1 + pd1));
            g_denom[gw * 4 + 2] = expf(lrelu(ps2 + pd2));
            g_denom[gw * 4 + 3] = expf(lrelu(ps3 + pd3));
        }
    } else {
        float s = wsum(ps0 + ps1 + ps2 + ps3);
        float d = wsum(pd0 + pd1 + pd2 + pd3);
        if (lane == 0) {
            g_asrc[gw] = s;
            g_adst[gw] = d;
            g_denom[gw] = expf(lrelu(s + d));
        }
    }
}

// ---------------- edge pass 1: accumulate softmax denominator ---------------
template<int H>
__global__ __launch_bounds__(256, 1)
void edge_denom_k(const int* __restrict__ ei)
{
    int t = blockIdx.x * blockDim.x + threadIdx.x;
    if (t >= N_EDGES * H) return;
    int e = t / H, h = t - e * H;
    int s = ei[e], d = ei[N_EDGES + e];
    float al = lrelu(g_asrc[s * H + h] + g_adst[d * H + h]);
    atomicAdd(&g_denom[d * H + h], expf(al));
}

// ---------------- self-loop contribution (initializes g_out) ----------------
template<int H>
__global__ __launch_bounds__(256, 1)
void self_out_k()
{
    int t = blockIdx.x * blockDim.x + threadIdx.x;
    int n = t >> 5, c4 = t & 31;
    if (n >= N_NODES) return;
    int c = c4 * 4;
    int h = (H == 4) ? (c4 >> 3) : 0;
    float al = lrelu(g_asrc[n * H + h] + g_adst[n * H + h]);
    float w  = expf(al) / (g_denom[n * H + h] + 1e-16f);
    float4 v = *(const float4*)(g_xw + (size_t)n * DIM + c);
    v.x *= w; v.y *= w; v.z *= w; v.w *= w;
    *(float4*)(g_out + (size_t)n * DIM + c) = v;
}

// ---------------- edge pass 2: weighted scatter-add -------------------------
template<int H>
__global__ __launch_bounds__(256, 1)
void edge_scatter_k(const int* __restrict__ ei)
{
    int e    = (blockIdx.x * blockDim.x + threadIdx.x) >> 5;
    int lane = threadIdx.x & 31;
    if (e >= N_EDGES) return;
    int s = ei[e], d = ei[N_EDGES + e];
    int c = lane * 4;
    int h = (H == 4) ? (lane >> 3) : 0;
    float al = lrelu(g_asrc[s * H + h] + g_adst[d * H + h]);
    float w  = expf(al) / (g_denom[d * H + h] + 1e-16f);
    float4 v = *(const float4*)(g_xw + (size_t)s * DIM + c);
    float* o = g_out + (size_t)d * DIM + c;
    atomicAdd(o + 0, w * v.x);
    atomicAdd(o + 1, w * v.y);
    atomicAdd(o + 2, w * v.z);
    atomicAdd(o + 3, w * v.w);
}

// ---------------- final: gather, elu, dot, sigmoid --------------------------
__global__ __launch_bounds__(256, 1)
void final_k(const int* __restrict__ uidx, const int* __restrict__ iidx,
             const float* __restrict__ bias2, float* __restrict__ res)
{
    int b    = (blockIdx.x * blockDim.x + threadIdx.x) >> 5;
    int lane = threadIdx.x & 31;
    if (b >= BATCH) return;
    int u = uidx[b];
    int v = iidx[b] + NUM_USERS;
    const float* ru = g_out + (size_t)u * DIM;
    const float* rv = g_out + (size_t)v * DIM;
    float bq0 = bias2[lane];      float bq1 = bias2[lane + 32];
    float bq2 = bias2[lane + 64]; float bq3 = bias2[lane + 96];
    float dot = eluf(ru[lane]      + bq0) * eluf(rv[lane]      + bq0)
              + eluf(ru[lane + 32] + bq1) * eluf(rv[lane + 32] + bq1)
              + eluf(ru[lane + 64] + bq2) * eluf(rv[lane + 64] + bq2)
              + eluf(ru[lane + 96] + bq3) * eluf(rv[lane + 96] + bq3);
    dot = wsum(dot);
    if (lane == 0) res[b] = 1.f / (1.f + expf(-dot));
}

// ---------------- launch -----------------------------------------------------
extern "C" void kernel_launch(void* const* d_in, const int* in_sizes, int n_in,
                              void* d_out, int out_size)
{
    const int*   uidx  = (const int*)  d_in[0];
    const int*   iidx  = (const int*)  d_in[1];
    const int*   ei    = (const int*)  d_in[2];
    const float* userT = (const float*)d_in[3];
    const float* itemT = (const float*)d_in[4];
    const float* W1    = (const float*)d_in[5];
    const float* attS1 = (const float*)d_in[6];
    const float* attD1 = (const float*)d_in[7];
    const float* bias1 = (const float*)d_in[8];
    const float* W2    = (const float*)d_in[9];
    const float* attS2 = (const float*)d_in[10];
    const float* attD2 = (const float*)d_in[11];
    const float* bias2 = (const float*)d_in[12];
    float* res = (float*)d_out;

    const int gemm_blocks = (N_NODES + BM - 1) / BM;           // 1732
    const int node_warps  = (N_NODES + 7) / 8;                 // blocks of 256 (8 warps)
    const int edge_warps  = (N_EDGES * 32 + 255) / 256;        // 12500
    const int batch_warps = (BATCH + 7) / 8;                   // 2048

    // ---- layer 1 (H=4) ----
    gemm_k<0><<<gemm_blocks, 256>>>(userT, itemT, nullptr, W1);
    scores_k<4><<<node_warps, 256>>>(attS1, attD1);
    edge_denom_k<4><<<(N_EDGES * 4 + 255) / 256, 256>>>(ei);
    self_out_k<4><<<node_warps, 256>>>();
    edge_scatter_k<4><<<edge_warps, 256>>>(ei);

    // ---- layer 2 (H=1); A = elu(g_out + bias1) fused into GEMM load ----
    gemm_k<1><<<gemm_blocks, 256>>>(userT, itemT, bias1, W2);
    scores_k<1><<<node_warps, 256>>>(attS2, attD2);
    edge_denom_k<1><<<(N_EDGES + 255) / 256, 256>>>(ei);
    self_out_k<1><<<node_warps, 256>>>();
    edge_scatter_k<1><<<edge_warps, 256>>>(ei);

    // ---- final embedding dot + sigmoid (elu+bias2 fused) ----
    final_k<<<batch_warps, 256>>>(uidx, iidx, bias2, res);
}

// round 5
// speedup vs baseline: 1.1855x; 1.1855x over previous
#include <cuda_runtime.h>
#include <math.h>
#include <stdint.h>

#define NUM_USERS 162541
#define NUM_ITEMS 59047
#define N_NODES   221588
#define DIM       128
#define N_EDGES   100000
#define BATCH     16384

// ---------------- scratch (device globals; device-code use ONLY) ------------
__device__ float g_xw [(size_t)N_NODES * DIM];   // x @ W (layer output pre-agg)
__device__ float g_out[(size_t)N_NODES * DIM];   // unnormalized aggregation
__device__ float g_asrc[N_NODES * 4];
__device__ float g_adst[N_NODES * 4];
__device__ float g_den1[N_NODES * 4];            // layer-1 softmax denominators
__device__ float g_den2[N_NODES];                // layer-2 softmax denominators
__device__ unsigned char g_need[N_NODES];        // batch-needed node mask

// ---------------- helpers ---------------------------------------------------
__device__ __forceinline__ float eluf(float x)  { return x > 0.f ? x : expm1f(x); }
__device__ __forceinline__ float lrelu(float x) { return x > 0.f ? x : 0.2f * x; }
__device__ __forceinline__ float wsum(float v) {
    #pragma unroll
    for (int o = 16; o; o >>= 1) v += __shfl_xor_sync(0xffffffffu, v, o);
    return v;
}
__device__ __forceinline__ uint32_t f2tf(float x) {
    uint32_t r; asm("cvt.rna.tf32.f32 %0, %1;" : "=r"(r) : "f"(x)); return r;
}
__device__ __forceinline__ void mma8(float& c0, float& c1, float& c2, float& c3,
    uint32_t a0, uint32_t a1, uint32_t a2, uint32_t a3, uint32_t b0, uint32_t b1) {
    asm volatile("mma.sync.aligned.m16n8k8.row.col.f32.tf32.tf32.f32 "
        "{%0,%1,%2,%3}, {%4,%5,%6,%7}, {%8,%9}, {%0,%1,%2,%3};\n"
        : "+f"(c0), "+f"(c1), "+f"(c2), "+f"(c3)
        : "r"(a0), "r"(a1), "r"(a2), "r"(a3), "r"(b0), "r"(b1));
}

// ---------------- 3xTF32 tensor-core GEMM + fused scores --------------------
// g_xw[M,128] = A[M,128] @ W[128,128]
// MODE 0: A row = concat tables;                fused H=4 scores + den1 seed
// MODE 1: A row = elu(g_out/den1 + biasPrev);   fused H=1 scores + den2 seed
template<int MODE>
__global__ __launch_bounds__(256)
void gemm_tc(const float* __restrict__ userT, const float* __restrict__ itemT,
             const float* __restrict__ biasPrev, const float* __restrict__ W,
             const float* __restrict__ attS, const float* __restrict__ attD)
{
    __shared__ float sA[2][16][136];   // [hi/lo][k][row], stride 136: conflict-free frag loads
    __shared__ float sB[2][16][136];   // [hi/lo][k][col]
    __shared__ float sS[4][128];       // per-nwarp score partials
    __shared__ float sD[4][128];

    const int tid  = threadIdx.x;
    const int row0 = blockIdx.x * 128;
    const int lane = tid & 31, qc = lane & 3, qg = lane >> 2;
    const int wid  = tid >> 5, wm = wid >> 2, wn = wid & 3;   // 2(m) x 4(n) warps

    // loader indexing
    const int lr  = tid >> 1;          // A tile row 0..127
    const int lh  = (tid & 1) * 8;     // A tile col offset {0,8}
    const int bkr = tid >> 4;          // B tile k row 0..15
    const int bc  = (tid & 15) * 8;    // B tile col
    const int agr = row0 + lr;

    float acc[4][4][4];
    #pragma unroll
    for (int i = 0; i < 4; i++)
        #pragma unroll
        for (int j = 0; j < 4; j++)
            #pragma unroll
            for (int k = 0; k < 4; k++) acc[i][j][k] = 0.f;

    float4 rA0, rA1, rB0, rB1;

    auto loadAB = [&](int ch) {
        const int kk = ch * 16;
        rB0 = *(const float4*)(W + (kk + bkr) * DIM + bc);
        rB1 = *(const float4*)(W + (kk + bkr) * DIM + bc + 4);
        if (agr < N_NODES) {
            if (MODE == 0) {
                const float* p = (agr < NUM_USERS)
                    ? userT + (size_t)agr * DIM
                    : itemT + (size_t)(agr - NUM_USERS) * DIM;
                rA0 = *(const float4*)(p + kk + lh);
                rA1 = *(const float4*)(p + kk + lh + 4);
            } else {
                const float* p = g_out + (size_t)agr * DIM + kk + lh;
                float4 v0 = *(const float4*)(p);
                float4 v1 = *(const float4*)(p + 4);
                float inv = 1.f / (g_den1[agr * 4 + ((kk + lh) >> 5)] + 1e-16f);
                float4 b0 = *(const float4*)(biasPrev + kk + lh);
                float4 b1 = *(const float4*)(biasPrev + kk + lh + 4);
                rA0.x = eluf(fmaf(v0.x, inv, b0.x)); rA0.y = eluf(fmaf(v0.y, inv, b0.y));
                rA0.z = eluf(fmaf(v0.z, inv, b0.z)); rA0.w = eluf(fmaf(v0.w, inv, b0.w));
                rA1.x = eluf(fmaf(v1.x, inv, b1.x)); rA1.y = eluf(fmaf(v1.y, inv, b1.y));
                rA1.z = eluf(fmaf(v1.z, inv, b1.z)); rA1.w = eluf(fmaf(v1.w, inv, b1.w));
            }
        } else {
            rA0 = make_float4(0.f, 0.f, 0.f, 0.f);
            rA1 = make_float4(0.f, 0.f, 0.f, 0.f);
        }
    };

    auto storeAB = [&]() {
        float av0[4] = {rA0.x, rA0.y, rA0.z, rA0.w};
        float av1[4] = {rA1.x, rA1.y, rA1.z, rA1.w};
        #pragma unroll
        for (int j = 0; j < 4; j++) {
            uint32_t h0 = f2tf(av0[j]);
            sA[0][lh + j][lr] = __uint_as_float(h0);
            sA[1][lh + j][lr] = __uint_as_float(f2tf(av0[j] - __uint_as_float(h0)));
            uint32_t h1 = f2tf(av1[j]);
            sA[0][lh + 4 + j][lr] = __uint_as_float(h1);
            sA[1][lh + 4 + j][lr] = __uint_as_float(f2tf(av1[j] - __uint_as_float(h1)));
        }
        float4 h4, l4;
        h4.x = __uint_as_float(f2tf(rB0.x)); l4.x = __uint_as_float(f2tf(rB0.x - h4.x));
        h4.y = __uint_as_float(f2tf(rB0.y)); l4.y = __uint_as_float(f2tf(rB0.y - h4.y));
        h4.z = __uint_as_float(f2tf(rB0.z)); l4.z = __uint_as_float(f2tf(rB0.z - h4.z));
        h4.w = __uint_as_float(f2tf(rB0.w)); l4.w = __uint_as_float(f2tf(rB0.w - h4.w));
        *(float4*)&sB[0][bkr][bc] = h4;
        *(float4*)&sB[1][bkr][bc] = l4;
        h4.x = __uint_as_float(f2tf(rB1.x)); l4.x = __uint_as_float(f2tf(rB1.x - h4.x));
        h4.y = __uint_as_float(f2tf(rB1.y)); l4.y = __uint_as_float(f2tf(rB1.y - h4.y));
        h4.z = __uint_as_float(f2tf(rB1.z)); l4.z = __uint_as_float(f2tf(rB1.z - h4.z));
        h4.w = __uint_as_float(f2tf(rB1.w)); l4.w = __uint_as_float(f2tf(rB1.w - h4.w));
        *(float4*)&sB[0][bkr][bc + 4] = h4;
        *(float4*)&sB[1][bkr][bc + 4] = l4;
    };

    loadAB(0);
    storeAB();
    __syncthreads();

    #pragma unroll 1
    for (int ch = 0; ch < 8; ch++) {
        if (ch < 7) loadAB(ch + 1);       // prefetch next chunk into registers

        #pragma unroll
        for (int ks = 0; ks < 16; ks += 8) {
            uint32_t bh[4][2], bl[4][2];
            #pragma unroll
            for (int ni = 0; ni < 4; ni++) {
                int n0 = wn * 32 + ni * 8 + qg;
                bh[ni][0] = __float_as_uint(sB[0][ks + qc][n0]);
                bh[ni][1] = __float_as_uint(sB[0][ks + qc + 4][n0]);
                bl[ni][0] = __float_as_uint(sB[1][ks + qc][n0]);
                bl[ni][1] = __float_as_uint(sB[1][ks + qc + 4][n0]);
            }
            #pragma unroll
            for (int mi = 0; mi < 4; mi++) {
                int r = wm * 64 + mi * 16 + qg;
                uint32_t ah0 = __float_as_uint(sA[0][ks + qc][r]);
                uint32_t ah1 = __float_as_uint(sA[0][ks + qc][r + 8]);
                uint32_t ah2 = __float_as_uint(sA[0][ks + qc + 4][r]);
                uint32_t ah3 = __float_as_uint(sA[0][ks + qc + 4][r + 8]);
                uint32_t al0 = __float_as_uint(sA[1][ks + qc][r]);
                uint32_t al1 = __float_as_uint(sA[1][ks + qc][r + 8]);
                uint32_t al2 = __float_as_uint(sA[1][ks + qc + 4][r]);
                uint32_t al3 = __float_as_uint(sA[1][ks + qc + 4][r + 8]);
                #pragma unroll
                for (int ni = 0; ni < 4; ni++) {
                    mma8(acc[mi][ni][0], acc[mi][ni][1], acc[mi][ni][2], acc[mi][ni][3],
                         ah0, ah1, ah2, ah3, bh[ni][0], bh[ni][1]);
                    mma8(acc[mi][ni][0], acc[mi][ni][1], acc[mi][ni][2], acc[mi][ni][3],
                         al0, al1, al2, al3, bh[ni][0], bh[ni][1]);
                    mma8(acc[mi][ni][0], acc[mi][ni][1], acc[mi][ni][2], acc[mi][ni][3],
                         ah0, ah1, ah2, ah3, bl[ni][0], bl[ni][1]);
                }
            }
        }
        __syncthreads();
        if (ch < 7) { storeAB(); __syncthreads(); }
    }

    // ---- epilogue: store xw + fused attention scores ----
    float wS0[4], wS1[4], wD0[4], wD1[4];
    #pragma unroll
    for (int ni = 0; ni < 4; ni++) {
        int cb = wn * 32 + ni * 8 + 2 * qc;
        wS0[ni] = attS[cb]; wS1[ni] = attS[cb + 1];
        wD0[ni] = attD[cb]; wD1[ni] = attD[cb + 1];
    }
    #pragma unroll
    for (int mi = 0; mi < 4; mi++) {
        int rl = row0 + wm * 64 + mi * 16 + qg;
        int rh = rl + 8;
        float psl = 0.f, pdl = 0.f, psh = 0.f, pdh = 0.f;
        #pragma unroll
        for (int ni = 0; ni < 4; ni++) {
            int col = wn * 32 + ni * 8 + 2 * qc;
            if (rl < N_NODES)
                *(float2*)(g_xw + (size_t)rl * DIM + col) =
                    make_float2(acc[mi][ni][0], acc[mi][ni][1]);
            if (rh < N_NODES)
                *(float2*)(g_xw + (size_t)rh * DIM + col) =
                    make_float2(acc[mi][ni][2], acc[mi][ni][3]);
            psl += acc[mi][ni][0] * wS0[ni] + acc[mi][ni][1] * wS1[ni];
            pdl += acc[mi][ni][0] * wD0[ni] + acc[mi][ni][1] * wD1[ni];
            psh += acc[mi][ni][2] * wS0[ni] + acc[mi][ni][3] * wS1[ni];
            pdh += acc[mi][ni][2] * wD0[ni] + acc[mi][ni][3] * wD1[ni];
        }
        psl += __shfl_xor_sync(~0u, psl, 1); psl += __shfl_xor_sync(~0u, psl, 2);
        pdl += __shfl_xor_sync(~0u, pdl, 1); pdl += __shfl_xor_sync(~0u, pdl, 2);
        psh += __shfl_xor_sync(~0u, psh, 1); psh += __shfl_xor_sync(~0u, psh, 2);
        pdh += __shfl_xor_sync(~0u, pdh, 1); pdh += __shfl_xor_sync(~0u, pdh, 2);
        if (qc == 0) {
            int lr0 = wm * 64 + mi * 16 + qg;
            sS[wn][lr0] = psl; sS[wn][lr0 + 8] = psh;
            sD[wn][lr0] = pdl; sD[wn][lr0 + 8] = pdh;
        }
    }
    __syncthreads();

    if (tid < 128) {
        int gr = row0 + tid;
        if (gr < N_NODES) {
            if (MODE == 0) {      // H=4: head == n-warp index
                #pragma unroll
                for (int h = 0; h < 4; h++) {
                    float s = sS[h][tid], d = sD[h][tid];
                    g_asrc[gr * 4 + h] = s;
                    g_adst[gr * 4 + h] = d;
                    g_den1[gr * 4 + h] = expf(lrelu(s + d));   // self-loop seed
                }
            } else {              // H=1: sum across the 4 n-warps
                float s = sS[0][tid] + sS[1][tid] + sS[2][tid] + sS[3][tid];
                float d = sD[0][tid] + sD[1][tid] + sD[2][tid] + sD[3][tid];
                g_asrc[gr] = s;
                g_adst[gr] = d;
                g_den2[gr] = expf(lrelu(s + d));               // self-loop seed
            }
        }
    }
}

// ---------------- self-loop contribution (unnormalized; inits g_out) --------
template<int H, bool GATED>
__global__ __launch_bounds__(256)
void self_out_k()
{
    int t = blockIdx.x * blockDim.x + threadIdx.x;
    int n = t >> 5, c4 = t & 31;
    if (n >= N_NODES) return;
    if (GATED && !g_need[n]) return;
    int c = c4 * 4;
    int h = (H == 4) ? (c4 >> 3) : 0;
    float w = expf(lrelu(g_asrc[n * H + h] + g_adst[n * H + h]));
    float4 v = *(const float4*)(g_xw + (size_t)n * DIM + c);
    v.x *= w; v.y *= w; v.z *= w; v.w *= w;
    *(float4*)(g_out + (size_t)n * DIM + c) = v;
}

// ---------------- single edge pass: denom atomics + weighted scatter --------
template<int H, bool GATED>
__global__ __launch_bounds__(256)
void edge_all_k(const int* __restrict__ ei)
{
    int e    = (blockIdx.x * blockDim.x + threadIdx.x) >> 5;
    int lane = threadIdx.x & 31;
    if (e >= N_EDGES) return;
    int d = ei[N_EDGES + e];
    if (GATED && !g_need[d]) return;
    int s = ei[e];
    int c = lane * 4;
    int h = (H == 4) ? (lane >> 3) : 0;
    float w = expf(lrelu(g_asrc[s * H + h] + g_adst[d * H + h]));
    if (H == 4) {
        if ((lane & 7) == 0) atomicAdd(&g_den1[d * 4 + h], w);
    } else {
        if (lane == 0) atomicAdd(&g_den2[d], w);
    }
    float4 v = *(const float4*)(g_xw + (size_t)s * DIM + c);
    float* o = g_out + (size_t)d * DIM + c;
    atomicAdd(o + 0, w * v.x);
    atomicAdd(o + 1, w * v.y);
    atomicAdd(o + 2, w * v.z);
    atomicAdd(o + 3, w * v.w);
}

// ---------------- batch-needed node mask -------------------------------------
__global__ __launch_bounds__(256)
void zero_need_k()
{
    int i = blockIdx.x * blockDim.x + threadIdx.x;
    if (i < N_NODES) g_need[i] = 0;
}
__global__ __launch_bounds__(256)
void set_need_k(const int* __restrict__ uidx, const int* __restrict__ iidx)
{
    int i = blockIdx.x * blockDim.x + threadIdx.x;
    if (i < BATCH) {
        g_need[uidx[i]] = 1;
        g_need[iidx[i] + NUM_USERS] = 1;
    }
}

// ---------------- final: gather, normalize, elu, dot, sigmoid ---------------
__global__ __launch_bounds__(256)
void final_k(const int* __restrict__ uidx, const int* __restrict__ iidx,
             const float* __restrict__ bias2, float* __restrict__ res)
{
    int b    = (blockIdx.x * blockDim.x + threadIdx.x) >> 5;
    int lane = threadIdx.x & 31;
    if (b >= BATCH) return;
    int u = uidx[b];
    int v = iidx[b] + NUM_USERS;
    float invu = 1.f / (g_den2[u] + 1e-16f);
    float invv = 1.f / (g_den2[v] + 1e-16f);
    const float* ru = g_out + (size_t)u * DIM;
    const float* rv = g_out + (size_t)v * DIM;
    float bq0 = bias2[lane];      float bq1 = bias2[lane + 32];
    float bq2 = bias2[lane + 64]; float bq3 = bias2[lane + 96];
    float dot =
        eluf(fmaf(ru[lane],      invu, bq0)) * eluf(fmaf(rv[lane],      invv, bq0)) +
        eluf(fmaf(ru[lane + 32], invu, bq1)) * eluf(fmaf(rv[lane + 32], invv, bq1)) +
        eluf(fmaf(ru[lane + 64], invu, bq2)) * eluf(fmaf(rv[lane + 64], invv, bq2)) +
        eluf(fmaf(ru[lane + 96], invu, bq3)) * eluf(fmaf(rv[lane + 96], invv, bq3));
    dot = wsum(dot);
    if (lane == 0) res[b] = 1.f / (1.f + expf(-dot));
}

// ---------------- launch -----------------------------------------------------
extern "C" void kernel_launch(void* const* d_in, const int* in_sizes, int n_in,
                              void* d_out, int out_size)
{
    const int*   uidx  = (const int*)  d_in[0];
    const int*   iidx  = (const int*)  d_in[1];
    const int*   ei    = (const int*)  d_in[2];
    const float* userT = (const float*)d_in[3];
    const float* itemT = (const float*)d_in[4];
    const float* W1    = (const float*)d_in[5];
    const float* attS1 = (const float*)d_in[6];
    const float* attD1 = (const float*)d_in[7];
    const float* bias1 = (const float*)d_in[8];
    const float* W2    = (const float*)d_in[9];
    const float* attS2 = (const float*)d_in[10];
    const float* attD2 = (const float*)d_in[11];
    const float* bias2 = (const float*)d_in[12];
    float* res = (float*)d_out;

    const int gemm_blocks = (N_NODES + 127) / 128;    // 1732
    const int node_warps  = (N_NODES + 7) / 8;        // 32 thr/node, blocks of 256
    const int edge_warps  = (N_EDGES * 32 + 255) / 256;
    const int batch_warps = (BATCH + 7) / 8;

    // ---- layer 1 (H=4): GEMM w/ fused scores -> self (unnorm) -> edges ----
    gemm_tc<0><<<gemm_blocks, 256>>>(userT, itemT, nullptr, W1, attS1, attD1);
    self_out_k<4, false><<<node_warps, 256>>>();
    edge_all_k<4, false><<<edge_warps, 256>>>(ei);

    // ---- batch mask (independent of layer-1 results) ----
    zero_need_k<<<(N_NODES + 255) / 256, 256>>>();
    set_need_k<<<(BATCH + 255) / 256, 256>>>(uidx, iidx);

    // ---- layer 2 (H=1): normalization folded into GEMM A-load; gated agg ----
    gemm_tc<1><<<gemm_blocks, 256>>>(userT, itemT, bias1, W2, attS2, attD2);
    self_out_k<1, true><<<node_warps, 256>>>();
    edge_all_k<1, true><<<edge_warps, 256>>>(ei);

    // ---- final: normalize + elu + dot + sigmoid ----
    final_k<<<batch_warps, 256>>>(uidx, iidx, bias2, res);
}

// round 6
// speedup vs baseline: 1.8813x; 1.5870x over previous
#include <cuda_runtime.h>
#include <math.h>
#include <stdint.h>

#define NUM_USERS 162541
#define NUM_ITEMS 59047
#define N_NODES   221588
#define DIM       128
#define N_EDGES   100000
#define BATCH     16384
#define MAXL1     132768    // max |need1| = 32768 batch + 100000 edge srcs
#define MAXL2     32768     // max |need2|

// ---------------- scratch (device globals; device-code use ONLY) ------------
// g_big: layer-1 per-head aggregates aggH[n][h][128]; after gemm1 it is reused
// as layer-2 aggregate agg2[n][128] (first quarter).
__device__ float g_big[(size_t)N_NODES * 512];
__device__ float g_h1 [(size_t)N_NODES * DIM];   // h1 = elu(out1/den1+bias1); later h2
__device__ float g_a1[N_NODES * 4], g_b1[N_NODES * 4];
__device__ float g_a2[N_NODES],     g_b2[N_NODES];
__device__ float g_den1[N_NODES * 4], g_den2[N_NODES];
__device__ unsigned char g_need1[N_NODES], g_need2[N_NODES], g_sc1[N_NODES];
__device__ int   g_list1[MAXL1], g_list2[MAXL2];
__device__ int   g_cnt1, g_cnt2;
__device__ float g_ws1[4 * DIM], g_wd1[4 * DIM];  // [h][k]: W1-block @ att1 per head
__device__ float g_ws2[DIM],     g_wd2[DIM];      // W2 @ att2

// ---------------- helpers ---------------------------------------------------
__device__ __forceinline__ float eluf(float x)  { return x > 0.f ? x : expm1f(x); }
__device__ __forceinline__ float lrelu(float x) { return x > 0.f ? x : 0.2f * x; }
__device__ __forceinline__ float wsum(float v) {
    #pragma unroll
    for (int o = 16; o; o >>= 1) v += __shfl_xor_sync(0xffffffffu, v, o);
    return v;
}
__device__ __forceinline__ const float* xrow(int n, const float* uT, const float* iT) {
    return (n < NUM_USERS) ? uT + (size_t)n * DIM
                           : iT + (size_t)(n - NUM_USERS) * DIM;
}

// ---------------- 1: fold attention vectors through W ------------------------
__global__ void prep_k(const float* __restrict__ W1, const float* __restrict__ aS1,
                       const float* __restrict__ aD1, const float* __restrict__ W2,
                       const float* __restrict__ aS2, const float* __restrict__ aD2)
{
    int k = threadIdx.x;                     // 0..127
    #pragma unroll
    for (int h = 0; h < 4; h++) {
        float s = 0.f, d = 0.f;
        #pragma unroll
        for (int c = 0; c < 32; c++) {
            float w = W1[k * DIM + h * 32 + c];
            s = fmaf(w, aS1[h * 32 + c], s);
            d = fmaf(w, aD1[h * 32 + c], d);
        }
        g_ws1[h * DIM + k] = s;
        g_wd1[h * DIM + k] = d;
    }
    float s2 = 0.f, d2 = 0.f;
    for (int j = 0; j < DIM; j++) {
        float w = W2[k * DIM + j];
        s2 = fmaf(w, aS2[j], s2);
        d2 = fmaf(w, aD2[j], d2);
    }
    g_ws2[k] = s2;
    g_wd2[k] = d2;
}

// ---------------- 2: reset masks + counters ---------------------------------
__global__ void zero_k()
{
    int i = blockIdx.x * blockDim.x + threadIdx.x;
    if (i < N_NODES) { g_need1[i] = 0; g_need2[i] = 0; g_sc1[i] = 0; }
    if (i == 0) { g_cnt1 = 0; g_cnt2 = 0; }
}

// ---------------- 3: mark batch nodes ---------------------------------------
__global__ void mark2_k(const int* __restrict__ uidx, const int* __restrict__ iidx)
{
    int i = blockIdx.x * blockDim.x + threadIdx.x;
    if (i >= BATCH) return;
    int u = uidx[i], v = iidx[i] + NUM_USERS;
    g_need2[u] = 1; g_need1[u] = 1;
    g_need2[v] = 1; g_need1[v] = 1;
}

// ---------------- 4: need1 |= srcs of edges into need2 ----------------------
__global__ void mark1_k(const int* __restrict__ ei)
{
    int e = blockIdx.x * blockDim.x + threadIdx.x;
    if (e >= N_EDGES) return;
    if (g_need2[ei[N_EDGES + e]]) g_need1[ei[e]] = 1;
}

// ---------------- 5: sc1 = srcs of edges into need1 (score-needed set) ------
__global__ void mark0_k(const int* __restrict__ ei)
{
    int e = blockIdx.x * blockDim.x + threadIdx.x;
    if (e >= N_EDGES) return;
    if (g_need1[ei[N_EDGES + e]]) g_sc1[ei[e]] = 1;
}

// ---------------- 6: layer-1 scores (gated matvec) + list compaction --------
__global__ __launch_bounds__(256)
void scores1_k(const float* __restrict__ uT, const float* __restrict__ iT)
{
    int n    = (blockIdx.x * blockDim.x + threadIdx.x) >> 5;
    int lane = threadIdx.x & 31;
    if (n >= N_NODES) return;
    unsigned char nd1 = g_need1[n];
    if (lane == 0) {
        if (nd1)        g_list1[atomicAdd(&g_cnt1, 1)] = n;
        if (g_need2[n]) g_list2[atomicAdd(&g_cnt2, 1)] = n;
    }
    if (!(nd1 | g_sc1[n])) return;
    const float* xr = xrow(n, uT, iT);
    float v0 = xr[lane];      float v1 = xr[lane + 32];
    float v2 = xr[lane + 64]; float v3 = xr[lane + 96];
    #pragma unroll
    for (int h = 0; h < 4; h++) {
        const float* ws = g_ws1 + h * DIM;
        const float* wd = g_wd1 + h * DIM;
        float s = v0 * ws[lane] + v1 * ws[lane + 32] + v2 * ws[lane + 64] + v3 * ws[lane + 96];
        float d = v0 * wd[lane] + v1 * wd[lane + 32] + v2 * wd[lane + 64] + v3 * wd[lane + 96];
        s = wsum(s); d = wsum(d);
        if (lane == 0) { g_a1[n * 4 + h] = s; g_b1[n * 4 + h] = d; }
    }
}

// ---------------- 7: layer-1 self-loop seed (agg in x-space) ----------------
__global__ __launch_bounds__(256)
void self1_k(const float* __restrict__ uT, const float* __restrict__ iT)
{
    int i    = (blockIdx.x * blockDim.x + threadIdx.x) >> 5;
    int lane = threadIdx.x & 31;
    if (i >= g_cnt1) return;
    int d = g_list1[i];
    const float* xr = xrow(d, uT, iT);
    float v0 = xr[lane];      float v1 = xr[lane + 32];
    float v2 = xr[lane + 64]; float v3 = xr[lane + 96];
    #pragma unroll
    for (int h = 0; h < 4; h++) {
        float w = expf(lrelu(g_a1[d * 4 + h] + g_b1[d * 4 + h]));
        if (lane == 0) g_den1[d * 4 + h] = w;
        float* o = g_big + ((size_t)(d * 4 + h)) * DIM;
        o[lane]      = w * v0;  o[lane + 32] = w * v1;
        o[lane + 64] = w * v2;  o[lane + 96] = w * v3;
    }
}

// ---------------- 8: layer-1 edge pass (gated; per-head x-space scatter) ----
__global__ __launch_bounds__(256)
void edge1_k(const int* __restrict__ ei,
             const float* __restrict__ uT, const float* __restrict__ iT)
{
    int e    = (blockIdx.x * blockDim.x + threadIdx.x) >> 5;
    int lane = threadIdx.x & 31;
    if (e >= N_EDGES) return;
    int d = ei[N_EDGES + e];
    if (!g_need1[d]) return;
    int s = ei[e];
    const float* xr = xrow(s, uT, iT);
    float v0 = xr[lane];      float v1 = xr[lane + 32];
    float v2 = xr[lane + 64]; float v3 = xr[lane + 96];
    #pragma unroll
    for (int h = 0; h < 4; h++) {
        float w = expf(lrelu(g_a1[s * 4 + h] + g_b1[d * 4 + h]));
        if (lane == 0) atomicAdd(&g_den1[d * 4 + h], w);
        float* o = g_big + ((size_t)(d * 4 + h)) * DIM;
        atomicAdd(o + lane,      w * v0);
        atomicAdd(o + lane + 32, w * v1);
        atomicAdd(o + lane + 64, w * v2);
        atomicAdd(o + lane + 96, w * v3);
    }
}

// ---------------- 9: small GEMM-1: h1 = elu(aggH @ W1 / den1 + bias1) -------
// warp per (node,head); lane = output column within 32-wide head block
__global__ __launch_bounds__(256)
void gemm1_k(const float* __restrict__ W1, const float* __restrict__ bias1)
{
    __shared__ float sm[8][DIM];
    int wi   = threadIdx.x >> 5;
    int lane = threadIdx.x & 31;
    int i    = blockIdx.x * 8 + wi;
    if (i >= g_cnt1 * 4) return;
    int d = g_list1[i >> 2], h = i & 3;
    const float* ar = g_big + ((size_t)(d * 4 + h)) * DIM;
    sm[wi][lane]      = ar[lane];      sm[wi][lane + 32] = ar[lane + 32];
    sm[wi][lane + 64] = ar[lane + 64]; sm[wi][lane + 96] = ar[lane + 96];
    __syncwarp();
    float acc = 0.f;
    int col = h * 32 + lane;
    #pragma unroll 8
    for (int k = 0; k < DIM; k++)
        acc = fmaf(sm[wi][k], W1[k * DIM + col], acc);
    float inv = 1.f / (g_den1[d * 4 + h] + 1e-16f);
    g_h1[(size_t)d * DIM + col] = eluf(fmaf(acc, inv, bias1[col]));
}

// ---------------- 10: layer-2 scores + self seed (agg2 aliases g_big) -------
__global__ __launch_bounds__(256)
void scores2_k()
{
    int i    = (blockIdx.x * blockDim.x + threadIdx.x) >> 5;
    int lane = threadIdx.x & 31;
    if (i >= g_cnt1) return;
    int d = g_list1[i];
    const float* hr = g_h1 + (size_t)d * DIM;
    float v0 = hr[lane];      float v1 = hr[lane + 32];
    float v2 = hr[lane + 64]; float v3 = hr[lane + 96];
    float s = v0 * g_ws2[lane] + v1 * g_ws2[lane + 32]
            + v2 * g_ws2[lane + 64] + v3 * g_ws2[lane + 96];
    float t = v0 * g_wd2[lane] + v1 * g_wd2[lane + 32]
            + v2 * g_wd2[lane + 64] + v3 * g_wd2[lane + 96];
    s = wsum(s); t = wsum(t);
    if (lane == 0) { g_a2[d] = s; g_b2[d] = t; }
    if (g_need2[d]) {
        float w = expf(lrelu(s + t));
        if (lane == 0) g_den2[d] = w;
        float* o = g_big + (size_t)d * DIM;      // agg2 region
        o[lane]      = w * v0;  o[lane + 32] = w * v1;
        o[lane + 64] = w * v2;  o[lane + 96] = w * v3;
    }
}

// ---------------- 11: layer-2 edge pass (gated; h1-space scatter) -----------
__global__ __launch_bounds__(256)
void edge2_k(const int* __restrict__ ei)
{
    int e    = (blockIdx.x * blockDim.x + threadIdx.x) >> 5;
    int lane = threadIdx.x & 31;
    if (e >= N_EDGES) return;
    int d = ei[N_EDGES + e];
    if (!g_need2[d]) return;
    int s = ei[e];
    float w = expf(lrelu(g_a2[s] + g_b2[d]));
    if (lane == 0) atomicAdd(&g_den2[d], w);
    const float* hr = g_h1 + (size_t)s * DIM;
    float* o = g_big + (size_t)d * DIM;
    atomicAdd(o + lane,      w * hr[lane]);
    atomicAdd(o + lane + 32, w * hr[lane + 32]);
    atomicAdd(o + lane + 64, w * hr[lane + 64]);
    atomicAdd(o + lane + 96, w * hr[lane + 96]);
}

// ---------------- 12: small GEMM-2: h2 = elu(agg2 @ W2 / den2 + bias2) ------
// warp per node; lane handles 4 output columns. h2 overwrites g_h1 rows.
__global__ __launch_bounds__(256)
void gemm2_k(const float* __restrict__ W2, const float* __restrict__ bias2)
{
    __shared__ float sm[8][DIM];
    int wi   = threadIdx.x >> 5;
    int lane = threadIdx.x & 31;
    int i    = blockIdx.x * 8 + wi;
    if (i >= g_cnt2) return;
    int d = g_list2[i];
    const float* ar = g_big + (size_t)d * DIM;
    sm[wi][lane]      = ar[lane];      sm[wi][lane + 32] = ar[lane + 32];
    sm[wi][lane + 64] = ar[lane + 64]; sm[wi][lane + 96] = ar[lane + 96];
    __syncwarp();
    float a0 = 0.f, a1 = 0.f, a2 = 0.f, a3 = 0.f;
    #pragma unroll 4
    for (int k = 0; k < DIM; k++) {
        float a = sm[wi][k];
        const float* wr = W2 + k * DIM;
        a0 = fmaf(a, wr[lane],      a0);
        a1 = fmaf(a, wr[lane + 32], a1);
        a2 = fmaf(a, wr[lane + 64], a2);
        a3 = fmaf(a, wr[lane + 96], a3);
    }
    float inv = 1.f / (g_den2[d] + 1e-16f);
    float* o = g_h1 + (size_t)d * DIM;           // h2 aliases h1
    o[lane]      = eluf(fmaf(a0, inv, bias2[lane]));
    o[lane + 32] = eluf(fmaf(a1, inv, bias2[lane + 32]));
    o[lane + 64] = eluf(fmaf(a2, inv, bias2[lane + 64]));
    o[lane + 96] = eluf(fmaf(a3, inv, bias2[lane + 96]));
}

// ---------------- 13: final dot + sigmoid ------------------------------------
__global__ __launch_bounds__(256)
void final_k(const int* __restrict__ uidx, const int* __restrict__ iidx,
             float* __restrict__ res)
{
    int b    = (blockIdx.x * blockDim.x + threadIdx.x) >> 5;
    int lane = threadIdx.x & 31;
    if (b >= BATCH) return;
    const float* ru = g_h1 + (size_t)uidx[b] * DIM;
    const float* rv = g_h1 + (size_t)(iidx[b] + NUM_USERS) * DIM;
    float dot = ru[lane]      * rv[lane]
              + ru[lane + 32] * rv[lane + 32]
              + ru[lane + 64] * rv[lane + 64]
              + ru[lane + 96] * rv[lane + 96];
    dot = wsum(dot);
    if (lane == 0) res[b] = 1.f / (1.f + expf(-dot));
}

// ---------------- launch -----------------------------------------------------
extern "C" void kernel_launch(void* const* d_in, const int* in_sizes, int n_in,
                              void* d_out, int out_size)
{
    const int*   uidx  = (const int*)  d_in[0];
    const int*   iidx  = (const int*)  d_in[1];
    const int*   ei    = (const int*)  d_in[2];
    const float* userT = (const float*)d_in[3];
    const float* itemT = (const float*)d_in[4];
    const float* W1    = (const float*)d_in[5];
    const float* attS1 = (const float*)d_in[6];
    const float* attD1 = (const float*)d_in[7];
    const float* bias1 = (const float*)d_in[8];
    const float* W2    = (const float*)d_in[9];
    const float* attS2 = (const float*)d_in[10];
    const float* attD2 = (const float*)d_in[11];
    const float* bias2 = (const float*)d_in[12];
    float* res = (float*)d_out;

    const int nodeW  = (N_NODES + 7) / 8;        // warp-per-node blocks
    const int edgeW  = (N_EDGES + 7) / 8;        // warp-per-edge blocks
    const int l1W    = (MAXL1 + 7) / 8;
    const int g1W    = (MAXL1 * 4 + 7) / 8;
    const int l2W    = (MAXL2 + 7) / 8;

    prep_k  <<<1, 128>>>(W1, attS1, attD1, W2, attS2, attD2);
    zero_k  <<<(N_NODES + 255) / 256, 256>>>();
    mark2_k <<<(BATCH + 255) / 256, 256>>>(uidx, iidx);
    mark1_k <<<(N_EDGES + 255) / 256, 256>>>(ei);
    mark0_k <<<(N_EDGES + 255) / 256, 256>>>(ei);

    scores1_k<<<nodeW, 256>>>(userT, itemT);
    self1_k  <<<l1W,   256>>>(userT, itemT);
    edge1_k  <<<edgeW, 256>>>(ei, userT, itemT);
    gemm1_k  <<<g1W,   256>>>(W1, bias1);

    scores2_k<<<l1W,   256>>>();
    edge2_k  <<<edgeW, 256>>>(ei);
    gemm2_k  <<<l2W,   256>>>(W2, bias2);

    final_k  <<<(BATCH + 7) / 8, 256>>>(uidx, iidx, res);
}

// round 7
// speedup vs baseline: 2.7682x; 1.4714x over previous
#include <cuda_runtime.h>
#include <math.h>
#include <stdint.h>

#define NUM_USERS 162541
#define NUM_ITEMS 59047
#define N_NODES   221588
#define DIM       128
#define N_EDGES   100000
#define BATCH     16384
#define MAXL1     132768    // max |need1|
#define MAXL2     32768     // max |need2|

// ---------------- scratch (device globals; device-code use ONLY) ------------
__device__ float g_big[(size_t)N_NODES * 512];   // L1: aggH[n][h][128]; L2: agg2[n][128]
__device__ float g_h1 [(size_t)N_NODES * DIM];   // h1; later h2
__device__ float g_a1[N_NODES * 4], g_b1[N_NODES * 4];
__device__ float g_a2[N_NODES],     g_b2[N_NODES];
__device__ float g_den1[N_NODES * 4], g_den2[N_NODES];
__device__ unsigned char g_need1[N_NODES], g_need2[N_NODES], g_sc1[N_NODES];
__device__ int   g_list1[MAXL1], g_list2[MAXL2];
__device__ int   g_cnt1, g_cnt2;
__device__ float g_ws1[4 * DIM], g_wd1[4 * DIM];
__device__ float g_ws2[DIM],     g_wd2[DIM];

// ---------------- helpers ---------------------------------------------------
__device__ __forceinline__ float eluf(float x)  { return x > 0.f ? x : expm1f(x); }
__device__ __forceinline__ float lrelu(float x) { return x > 0.f ? x : 0.2f * x; }
__device__ __forceinline__ float wsum(float v) {
    #pragma unroll
    for (int o = 16; o; o >>= 1) v += __shfl_xor_sync(0xffffffffu, v, o);
    return v;
}
__device__ __forceinline__ const float* xrow(int n, const float* uT, const float* iT) {
    return (n < NUM_USERS) ? uT + (size_t)n * DIM
                           : iT + (size_t)(n - NUM_USERS) * DIM;
}

// ---------------- 1: fold attention vectors through W ------------------------
__global__ void prep_k(const float* __restrict__ W1, const float* __restrict__ aS1,
                       const float* __restrict__ aD1, const float* __restrict__ W2,
                       const float* __restrict__ aS2, const float* __restrict__ aD2)
{
    int k = threadIdx.x;                     // 0..127
    #pragma unroll
    for (int h = 0; h < 4; h++) {
        float s = 0.f, d = 0.f;
        #pragma unroll
        for (int c = 0; c < 32; c++) {
            float w = W1[k * DIM + h * 32 + c];
            s = fmaf(w, aS1[h * 32 + c], s);
            d = fmaf(w, aD1[h * 32 + c], d);
        }
        g_ws1[h * DIM + k] = s;
        g_wd1[h * DIM + k] = d;
    }
    float s2 = 0.f, d2 = 0.f;
    for (int j = 0; j < DIM; j++) {
        float w = W2[k * DIM + j];
        s2 = fmaf(w, aS2[j], s2);
        d2 = fmaf(w, aD2[j], d2);
    }
    g_ws2[k] = s2;
    g_wd2[k] = d2;
}

// ---------------- 2-5: masks ------------------------------------------------
__global__ void zero_k()
{
    int i = blockIdx.x * blockDim.x + threadIdx.x;
    if (i < N_NODES) { g_need1[i] = 0; g_need2[i] = 0; g_sc1[i] = 0; }
    if (i == 0) { g_cnt1 = 0; g_cnt2 = 0; }
}
__global__ void mark2_k(const int* __restrict__ uidx, const int* __restrict__ iidx)
{
    int i = blockIdx.x * blockDim.x + threadIdx.x;
    if (i >= BATCH) return;
    int u = uidx[i], v = iidx[i] + NUM_USERS;
    g_need2[u] = 1; g_need1[u] = 1;
    g_need2[v] = 1; g_need1[v] = 1;
}
__global__ void mark1_k(const int* __restrict__ ei)
{
    int e = blockIdx.x * blockDim.x + threadIdx.x;
    if (e >= N_EDGES) return;
    if (g_need2[ei[N_EDGES + e]]) g_need1[ei[e]] = 1;
}
__global__ void mark0_k(const int* __restrict__ ei)
{
    int e = blockIdx.x * blockDim.x + threadIdx.x;
    if (e >= N_EDGES) return;
    if (g_need1[ei[N_EDGES + e]]) g_sc1[ei[e]] = 1;
}

// ---------------- 6: layer-1 scores (gated matvec) + list compaction --------
__global__ __launch_bounds__(256)
void scores1_k(const float* __restrict__ uT, const float* __restrict__ iT)
{
    int n    = (blockIdx.x * blockDim.x + threadIdx.x) >> 5;
    int lane = threadIdx.x & 31;
    if (n >= N_NODES) return;
    unsigned char nd1 = g_need1[n];
    if (lane == 0) {
        if (nd1)        g_list1[atomicAdd(&g_cnt1, 1)] = n;
        if (g_need2[n]) g_list2[atomicAdd(&g_cnt2, 1)] = n;
    }
    if (!(nd1 | g_sc1[n])) return;
    const float* xr = xrow(n, uT, iT);
    float v0 = xr[lane];      float v1 = xr[lane + 32];
    float v2 = xr[lane + 64]; float v3 = xr[lane + 96];
    #pragma unroll
    for (int h = 0; h < 4; h++) {
        const float* ws = g_ws1 + h * DIM;
        const float* wd = g_wd1 + h * DIM;
        float s = v0 * ws[lane] + v1 * ws[lane + 32] + v2 * ws[lane + 64] + v3 * ws[lane + 96];
        float d = v0 * wd[lane] + v1 * wd[lane + 32] + v2 * wd[lane + 64] + v3 * wd[lane + 96];
        s = wsum(s); d = wsum(d);
        if (lane == 0) { g_a1[n * 4 + h] = s; g_b1[n * 4 + h] = d; }
    }
}

// ---------------- 7: layer-1 self-loop seed ----------------------------------
__global__ __launch_bounds__(256)
void self1_k(const float* __restrict__ uT, const float* __restrict__ iT)
{
    int i    = (blockIdx.x * blockDim.x + threadIdx.x) >> 5;
    int lane = threadIdx.x & 31;
    if (i >= g_cnt1) return;
    int d = g_list1[i];
    const float* xr = xrow(d, uT, iT);
    float v0 = xr[lane];      float v1 = xr[lane + 32];
    float v2 = xr[lane + 64]; float v3 = xr[lane + 96];
    #pragma unroll
    for (int h = 0; h < 4; h++) {
        float w = expf(lrelu(g_a1[d * 4 + h] + g_b1[d * 4 + h]));
        if (lane == 0) g_den1[d * 4 + h] = w;
        float* o = g_big + ((size_t)(d * 4 + h)) * DIM;
        o[lane]      = w * v0;  o[lane + 32] = w * v1;
        o[lane + 64] = w * v2;  o[lane + 96] = w * v3;
    }
}

// ---------------- 8: layer-1 edge pass ---------------------------------------
__global__ __launch_bounds__(256)
void edge1_k(const int* __restrict__ ei,
             const float* __restrict__ uT, const float* __restrict__ iT)
{
    int e    = (blockIdx.x * blockDim.x + threadIdx.x) >> 5;
    int lane = threadIdx.x & 31;
    if (e >= N_EDGES) return;
    int d = ei[N_EDGES + e];
    if (!g_need1[d]) return;
    int s = ei[e];
    const float* xr = xrow(s, uT, iT);
    float v0 = xr[lane];      float v1 = xr[lane + 32];
    float v2 = xr[lane + 64]; float v3 = xr[lane + 96];
    #pragma unroll
    for (int h = 0; h < 4; h++) {
        float w = expf(lrelu(g_a1[s * 4 + h] + g_b1[d * 4 + h]));
        if (lane == 0) atomicAdd(&g_den1[d * 4 + h], w);
        float* o = g_big + ((size_t)(d * 4 + h)) * DIM;
        atomicAdd(o + lane,      w * v0);
        atomicAdd(o + lane + 32, w * v1);
        atomicAdd(o + lane + 64, w * v2);
        atomicAdd(o + lane + 96, w * v3);
    }
}

// ---------------- 9: GEMM-1 (tiled): h1 = elu(aggH @ W1blk / den + bias) ----
// grid = (ceil(MAXL1/128), 4 heads); BM=128, BN=32, BK=32; 4x4 micro-tile.
__global__ __launch_bounds__(256)
void gemm1_k(const float* __restrict__ W1, const float* __restrict__ bias1)
{
    __shared__ float As[32][132];     // [k][row] transposed
    __shared__ float Bs[32][36];      // [k][col]
    __shared__ int   sNode[128];
    __shared__ float sInv[128];

    const int cnt  = g_cnt1;
    const int row0 = blockIdx.x * 128;
    if (row0 >= cnt) return;
    const int h   = blockIdx.y;
    const int tid = threadIdx.x;
    const int tx  = tid & 7;          // 8 col groups x 4 cols
    const int ty  = tid >> 3;         // 32 row groups x 4 rows

    if (tid < 128) {
        int r = row0 + tid;
        int node = (r < cnt) ? g_list1[r] : g_list1[0];
        sNode[tid] = node;
        sInv[tid]  = 1.f / (g_den1[node * 4 + h] + 1e-16f);
    }
    __syncthreads();

    float acc[4][4];
    #pragma unroll
    for (int i = 0; i < 4; i++)
        #pragma unroll
        for (int j = 0; j < 4; j++) acc[i][j] = 0.f;

    // loader mapping: lanes consecutive over rows -> conflict-free STS
    const int lr = tid & 127;         // A row
    const int lq = (tid >> 7) * 16;   // A col offset {0,16}
    const int bkr = tid >> 3;         // B k row 0..31
    const int bbc = (tid & 7) * 4;    // B col

    for (int kk = 0; kk < DIM; kk += 32) {
        const bool valid = (row0 + lr < cnt);
        const float* ap = g_big + ((size_t)(sNode[lr] * 4 + h)) * DIM + kk + lq;
        #pragma unroll
        for (int q = 0; q < 4; q++) {
            float4 v = valid ? *(const float4*)(ap + q * 4)
                             : make_float4(0.f, 0.f, 0.f, 0.f);
            As[lq + q * 4 + 0][lr] = v.x;
            As[lq + q * 4 + 1][lr] = v.y;
            As[lq + q * 4 + 2][lr] = v.z;
            As[lq + q * 4 + 3][lr] = v.w;
        }
        *(float4*)&Bs[bkr][bbc] =
            *(const float4*)(W1 + (size_t)(kk + bkr) * DIM + h * 32 + bbc);
        __syncthreads();

        #pragma unroll
        for (int k = 0; k < 32; k++) {
            float4 a4 = *(const float4*)&As[k][ty * 4];
            float4 b4 = *(const float4*)&Bs[k][tx * 4];
            float a[4] = {a4.x, a4.y, a4.z, a4.w};
            float b[4] = {b4.x, b4.y, b4.z, b4.w};
            #pragma unroll
            for (int i = 0; i < 4; i++)
                #pragma unroll
                for (int j = 0; j < 4; j++)
                    acc[i][j] = fmaf(a[i], b[j], acc[i][j]);
        }
        __syncthreads();
    }

    const int colb = h * 32 + tx * 4;
    float b0 = bias1[colb], b1 = bias1[colb + 1], b2 = bias1[colb + 2], b3 = bias1[colb + 3];
    #pragma unroll
    for (int i = 0; i < 4; i++) {
        int row = ty * 4 + i;
        if (row0 + row < cnt) {
            float inv = sInv[row];
            float* o = g_h1 + (size_t)sNode[row] * DIM + colb;
            *(float4*)o = make_float4(
                eluf(fmaf(acc[i][0], inv, b0)),
                eluf(fmaf(acc[i][1], inv, b1)),
                eluf(fmaf(acc[i][2], inv, b2)),
                eluf(fmaf(acc[i][3], inv, b3)));
        }
    }
}

// ---------------- 10: layer-2 scores + self seed -----------------------------
__global__ __launch_bounds__(256)
void scores2_k()
{
    int i    = (blockIdx.x * blockDim.x + threadIdx.x) >> 5;
    int lane = threadIdx.x & 31;
    if (i >= g_cnt1) return;
    int d = g_list1[i];
    const float* hr = g_h1 + (size_t)d * DIM;
    float v0 = hr[lane];      float v1 = hr[lane + 32];
    float v2 = hr[lane + 64]; float v3 = hr[lane + 96];
    float s = v0 * g_ws2[lane] + v1 * g_ws2[lane + 32]
            + v2 * g_ws2[lane + 64] + v3 * g_ws2[lane + 96];
    float t = v0 * g_wd2[lane] + v1 * g_wd2[lane + 32]
            + v2 * g_wd2[lane + 64] + v3 * g_wd2[lane + 96];
    s = wsum(s); t = wsum(t);
    if (lane == 0) { g_a2[d] = s; g_b2[d] = t; }
    if (g_need2[d]) {
        float w = expf(lrelu(s + t));
        if (lane == 0) g_den2[d] = w;
        float* o = g_big + (size_t)d * DIM;
        o[lane]      = w * v0;  o[lane + 32] = w * v1;
        o[lane + 64] = w * v2;  o[lane + 96] = w * v3;
    }
}

// ---------------- 11: layer-2 edge pass --------------------------------------
__global__ __launch_bounds__(256)
void edge2_k(const int* __restrict__ ei)
{
    int e    = (blockIdx.x * blockDim.x + threadIdx.x) >> 5;
    int lane = threadIdx.x & 31;
    if (e >= N_EDGES) return;
    int d = ei[N_EDGES + e];
    if (!g_need2[d]) return;
    int s = ei[e];
    float w = expf(lrelu(g_a2[s] + g_b2[d]));
    if (lane == 0) atomicAdd(&g_den2[d], w);
    const float* hr = g_h1 + (size_t)s * DIM;
    float* o = g_big + (size_t)d * DIM;
    atomicAdd(o + lane,      w * hr[lane]);
    atomicAdd(o + lane + 32, w * hr[lane + 32]);
    atomicAdd(o + lane + 64, w * hr[lane + 64]);
    atomicAdd(o + lane + 96, w * hr[lane + 96]);
}

// ---------------- 12: GEMM-2 (tiled): h2 = elu(agg2 @ W2 / den2 + bias2) ----
// BM=128, BN=128, BK=16; 8x8 micro-tile; A rows gathered via list2.
__global__ __launch_bounds__(256)
void gemm2_k(const float* __restrict__ W2, const float* __restrict__ bias2)
{
    __shared__ float As[16][132];
    __shared__ float Bs[16][128];
    __shared__ int   sNode[128];
    __shared__ float sInv[128];

    const int cnt  = g_cnt2;
    const int row0 = blockIdx.x * 128;
    if (row0 >= cnt) return;
    const int tid = threadIdx.x;
    const int tx  = tid & 15;         // 16 col groups x 8
    const int ty  = tid >> 4;         // 16 row groups x 8

    if (tid < 128) {
        int r = row0 + tid;
        int node = (r < cnt) ? g_list2[r] : g_list2[0];
        sNode[tid] = node;
        sInv[tid]  = 1.f / (g_den2[node] + 1e-16f);
    }
    __syncthreads();

    float acc[8][8];
    #pragma unroll
    for (int i = 0; i < 8; i++)
        #pragma unroll
        for (int j = 0; j < 8; j++) acc[i][j] = 0.f;

    const int lr = tid & 127;         // A row
    const int lq = (tid >> 7) * 8;    // A col offset {0,8}
    const int bkr = tid >> 4;         // B k row 0..15
    const int bbc = (tid & 15) * 8;   // B col

    for (int kk = 0; kk < DIM; kk += 16) {
        const bool valid = (row0 + lr < cnt);
        const float* ap = g_big + (size_t)sNode[lr] * DIM + kk + lq;
        #pragma unroll
        for (int q = 0; q < 2; q++) {
            float4 v = valid ? *(const float4*)(ap + q * 4)
                             : make_float4(0.f, 0.f, 0.f, 0.f);
            As[lq + q * 4 + 0][lr] = v.x;
            As[lq + q * 4 + 1][lr] = v.y;
            As[lq + q * 4 + 2][lr] = v.z;
            As[lq + q * 4 + 3][lr] = v.w;
        }
        *(float4*)&Bs[bkr][bbc]     = *(const float4*)(W2 + (size_t)(kk + bkr) * DIM + bbc);
        *(float4*)&Bs[bkr][bbc + 4] = *(const float4*)(W2 + (size_t)(kk + bkr) * DIM + bbc + 4);
        __syncthreads();

        #pragma unroll
        for (int k = 0; k < 16; k++) {
            float4 a0 = *(const float4*)&As[k][ty * 8];
            float4 a1 = *(const float4*)&As[k][ty * 8 + 4];
            float4 b0 = *(const float4*)&Bs[k][tx * 8];
            float4 b1 = *(const float4*)&Bs[k][tx * 8 + 4];
            float a[8] = {a0.x, a0.y, a0.z, a0.w, a1.x, a1.y, a1.z, a1.w};
            float b[8] = {b0.x, b0.y, b0.z, b0.w, b1.x, b1.y, b1.z, b1.w};
            #pragma unroll
            for (int i = 0; i < 8; i++)
                #pragma unroll
                for (int j = 0; j < 8; j++)
                    acc[i][j] = fmaf(a[i], b[j], acc[i][j]);
        }
        __syncthreads();
    }

    const int colb = tx * 8;
    float bb[8];
    #pragma unroll
    for (int j = 0; j < 8; j++) bb[j] = bias2[colb + j];
    #pragma unroll
    for (int i = 0; i < 8; i++) {
        int row = ty * 8 + i;
        if (row0 + row < cnt) {
            float inv = sInv[row];
            float* o = g_h1 + (size_t)sNode[row] * DIM + colb;   // h2 aliases h1
            *(float4*)(o) = make_float4(
                eluf(fmaf(acc[i][0], inv, bb[0])),
                eluf(fmaf(acc[i][1], inv, bb[1])),
                eluf(fmaf(acc[i][2], inv, bb[2])),
                eluf(fmaf(acc[i][3], inv, bb[3])));
            *(float4*)(o + 4) = make_float4(
                eluf(fmaf(acc[i][4], inv, bb[4])),
                eluf(fmaf(acc[i][5], inv, bb[5])),
                eluf(fmaf(acc[i][6], inv, bb[6])),
                eluf(fmaf(acc[i][7], inv, bb[7])));
        }
    }
}

// ---------------- 13: final dot + sigmoid ------------------------------------
__global__ __launch_bounds__(256)
void final_k(const int* __restrict__ uidx, const int* __restrict__ iidx,
             float* __restrict__ res)
{
    int b    = (blockIdx.x * blockDim.x + threadIdx.x) >> 5;
    int lane = threadIdx.x & 31;
    if (b >= BATCH) return;
    const float* ru = g_h1 + (size_t)uidx[b] * DIM;
    const float* rv = g_h1 + (size_t)(iidx[b] + NUM_USERS) * DIM;
    float dot = ru[lane]      * rv[lane]
              + ru[lane + 32] * rv[lane + 32]
              + ru[lane + 64] * rv[lane + 64]
              + ru[lane + 96] * rv[lane + 96];
    dot = wsum(dot);
    if (lane == 0) res[b] = 1.f / (1.f + expf(-dot));
}

// ---------------- launch -----------------------------------------------------
extern "C" void kernel_launch(void* const* d_in, const int* in_sizes, int n_in,
                              void* d_out, int out_size)
{
    const int*   uidx  = (const int*)  d_in[0];
    const int*   iidx  = (const int*)  d_in[1];
    const int*   ei    = (const int*)  d_in[2];
    const float* userT = (const float*)d_in[3];
    const float* itemT = (const float*)d_in[4];
    const float* W1    = (const float*)d_in[5];
    const float* attS1 = (const float*)d_in[6];
    const float* attD1 = (const float*)d_in[7];
    const float* bias1 = (const float*)d_in[8];
    const float* W2    = (const float*)d_in[9];
    const float* attS2 = (const float*)d_in[10];
    const float* attD2 = (const float*)d_in[11];
    const float* bias2 = (const float*)d_in[12];
    float* res = (float*)d_out;

    const int nodeW = (N_NODES + 7) / 8;
    const int edgeW = (N_EDGES + 7) / 8;
    const int l1W   = (MAXL1 + 7) / 8;

    prep_k  <<<1, 128>>>(W1, attS1, attD1, W2, attS2, attD2);
    zero_k  <<<(N_NODES + 255) / 256, 256>>>();
    mark2_k <<<(BATCH + 255) / 256, 256>>>(uidx, iidx);
    mark1_k <<<(N_EDGES + 255) / 256, 256>>>(ei);
    mark0_k <<<(N_EDGES + 255) / 256, 256>>>(ei);

    scores1_k<<<nodeW, 256>>>(userT, itemT);
    self1_k  <<<l1W,   256>>>(userT, itemT);
    edge1_k  <<<edgeW, 256>>>(ei, userT, itemT);
    gemm1_k  <<<dim3((MAXL1 + 127) / 128, 4), 256>>>(W1, bias1);

    scores2_k<<<l1W,   256>>>();
    edge2_k  <<<edgeW, 256>>>(ei);
    gemm2_k  <<<(MAXL2 + 127) / 128, 256>>>(W2, bias2);

    final_k  <<<(BATCH + 7) / 8, 256>>>(uidx, iidx, res);
}

// round 8
// speedup vs baseline: 2.9590x; 1.0689x over previous
#include <cuda_runtime.h>
#include <math.h>
#include <stdint.h>

#define NUM_USERS 162541
#define NUM_ITEMS 59047
#define N_NODES   221588
#define DIM       128
#define N_EDGES   100000
#define BATCH     16384
#define MAXL1     132768    // |need1| <= 32768 + 100000
#define MAXL2     32768     // |need2| <= 32768

// ---------------- scratch (device globals; device-code use ONLY) ------------
__device__ float g_big[(size_t)N_NODES * 512];   // L1: aggH[n][h][128]; L2: agg2[n][128]
__device__ float g_h1 [(size_t)N_NODES * DIM];   // h1; later h2
__device__ float g_a1[N_NODES * 4], g_b1[N_NODES * 4];
__device__ float g_a2[N_NODES],     g_b2[N_NODES];
__device__ unsigned char g_need1[N_NODES], g_need2[N_NODES], g_sc1[N_NODES];
__device__ int g_list1[MAXL1], g_list2[MAXL2], g_listS[N_NODES];
__device__ int g_cnt1, g_cnt2, g_cntS, g_tot1, g_tot2;
__device__ int g_deg1[N_NODES], g_deg2[N_NODES];
__device__ int g_base1[N_NODES], g_base2[N_NODES];
__device__ int g_fc1[N_NODES], g_fc2[N_NODES];
__device__ int g_csr1[N_EDGES], g_csr2[N_EDGES];
__device__ float g_ws1[4 * DIM], g_wd1[4 * DIM];
__device__ float g_ws2[DIM],     g_wd2[DIM];

// ---------------- helpers ---------------------------------------------------
__device__ __forceinline__ float eluf(float x)  { return x > 0.f ? x : expm1f(x); }
__device__ __forceinline__ float lrelu(float x) { return x > 0.f ? x : 0.2f * x; }
__device__ __forceinline__ float wsum(float v) {
    #pragma unroll
    for (int o = 16; o; o >>= 1) v += __shfl_xor_sync(0xffffffffu, v, o);
    return v;
}
__device__ __forceinline__ const float* xrow(int n, const float* uT, const float* iT) {
    return (n < NUM_USERS) ? uT + (size_t)n * DIM
                           : iT + (size_t)(n - NUM_USERS) * DIM;
}

// ---------------- 1: fold attention vectors through W ------------------------
__global__ void prep_k(const float* __restrict__ W1, const float* __restrict__ aS1,
                       const float* __restrict__ aD1, const float* __restrict__ W2,
                       const float* __restrict__ aS2, const float* __restrict__ aD2)
{
    int k = threadIdx.x;                     // 0..127
    #pragma unroll
    for (int h = 0; h < 4; h++) {
        float s = 0.f, d = 0.f;
        #pragma unroll
        for (int c = 0; c < 32; c++) {
            float w = W1[k * DIM + h * 32 + c];
            s = fmaf(w, aS1[h * 32 + c], s);
            d = fmaf(w, aD1[h * 32 + c], d);
        }
        g_ws1[h * DIM + k] = s;
        g_wd1[h * DIM + k] = d;
    }
    float s2 = 0.f, d2 = 0.f;
    for (int j = 0; j < DIM; j++) {
        float w = W2[k * DIM + j];
        s2 = fmaf(w, aS2[j], s2);
        d2 = fmaf(w, aD2[j], d2);
    }
    g_ws2[k] = s2;
    g_wd2[k] = d2;
}

// ---------------- 2: reset masks / counters / degree arrays -----------------
__global__ void zero_k()
{
    int i = blockIdx.x * blockDim.x + threadIdx.x;
    if (i < N_NODES) {
        g_need1[i] = 0; g_need2[i] = 0; g_sc1[i] = 0;
        g_deg1[i] = 0;  g_deg2[i] = 0;
        g_fc1[i] = 0;   g_fc2[i] = 0;
    }
    if (i == 0) { g_cnt1 = 0; g_cnt2 = 0; g_cntS = 0; g_tot1 = 0; g_tot2 = 0; }
}

// ---------------- 3-5: masks + degree histogram ------------------------------
__global__ void mark2_k(const int* __restrict__ uidx, const int* __restrict__ iidx)
{
    int i = blockIdx.x * blockDim.x + threadIdx.x;
    if (i >= BATCH) return;
    int u = uidx[i], v = iidx[i] + NUM_USERS;
    g_need2[u] = 1; g_need1[u] = 1;
    g_need2[v] = 1; g_need1[v] = 1;
}
__global__ void mark1_k(const int* __restrict__ ei)
{
    int e = blockIdx.x * blockDim.x + threadIdx.x;
    if (e >= N_EDGES) return;
    if (g_need2[ei[N_EDGES + e]]) g_need1[ei[e]] = 1;
}
__global__ void markC_k(const int* __restrict__ ei)   // sc1 marks + degree counts
{
    int e = blockIdx.x * blockDim.x + threadIdx.x;
    if (e >= N_EDGES) return;
    int d = ei[N_EDGES + e], s = ei[e];
    if (g_need1[d]) { g_sc1[s] = 1; atomicAdd(&g_deg1[d], 1); }
    if (g_need2[d]) { atomicAdd(&g_deg2[d], 1); }
}

// ---------------- 6: block-aggregated list compaction ------------------------
__global__ __launch_bounds__(256)
void compact_k()
{
    __shared__ int w1[8], w2[8], wS[8];
    __shared__ int base1, base2, baseS;
    int i = blockIdx.x * 256 + threadIdx.x;
    int w = threadIdx.x >> 5, lane = threadIdx.x & 31;
    bool in1 = (i < N_NODES) && g_need1[i];
    bool in2 = (i < N_NODES) && g_need2[i];
    bool inS = (i < N_NODES) && (g_need1[i] | g_sc1[i]);
    unsigned m1 = __ballot_sync(~0u, in1);
    unsigned m2 = __ballot_sync(~0u, in2);
    unsigned mS = __ballot_sync(~0u, inS);
    if (lane == 0) { w1[w] = __popc(m1); w2[w] = __popc(m2); wS[w] = __popc(mS); }
    __syncthreads();
    if (threadIdx.x == 0) {
        int t1 = 0, t2 = 0, tS = 0;
        #pragma unroll
        for (int k = 0; k < 8; k++) {
            int v1 = w1[k]; w1[k] = t1; t1 += v1;
            int v2 = w2[k]; w2[k] = t2; t2 += v2;
            int vS = wS[k]; wS[k] = tS; tS += vS;
        }
        base1 = atomicAdd(&g_cnt1, t1);
        base2 = atomicAdd(&g_cnt2, t2);
        baseS = atomicAdd(&g_cntS, tS);
    }
    __syncthreads();
    unsigned lm = (1u << lane) - 1u;
    if (in1) g_list1[base1 + w1[w] + __popc(m1 & lm)] = i;
    if (in2) g_list2[base2 + w2[w] + __popc(m2 & lm)] = i;
    if (inS) g_listS[baseS + wS[w] + __popc(mS & lm)] = i;
}

// ---------------- 7: warp-aggregated CSR base allocation ---------------------
__global__ __launch_bounds__(256)
void alloc_k()
{
    int i    = blockIdx.x * blockDim.x + threadIdx.x;
    int lane = threadIdx.x & 31;
    // list1 ranges
    {
        int cnt = g_cnt1;
        int deg = (i < cnt) ? g_deg1[g_list1[i]] : 0;
        int inc = deg;
        #pragma unroll
        for (int o = 1; o < 32; o <<= 1) {
            int t = __shfl_up_sync(~0u, inc, o);
            if (lane >= o) inc += t;
        }
        int tot = __shfl_sync(~0u, inc, 31);
        int wb = 0;
        if (lane == 31 && tot > 0) wb = atomicAdd(&g_tot1, tot);
        wb = __shfl_sync(~0u, wb, 31);
        if (i < cnt) g_base1[g_list1[i]] = wb + inc - deg;
    }
    // list2 ranges
    {
        int cnt = g_cnt2;
        int deg = (i < cnt) ? g_deg2[g_list2[i]] : 0;
        int inc = deg;
        #pragma unroll
        for (int o = 1; o < 32; o <<= 1) {
            int t = __shfl_up_sync(~0u, inc, o);
            if (lane >= o) inc += t;
        }
        int tot = __shfl_sync(~0u, inc, 31);
        int wb = 0;
        if (lane == 31 && tot > 0) wb = atomicAdd(&g_tot2, tot);
        wb = __shfl_sync(~0u, wb, 31);
        if (i < cnt) g_base2[g_list2[i]] = wb + inc - deg;
    }
}

// ---------------- 8: CSR fill -------------------------------------------------
__global__ void fill_k(const int* __restrict__ ei)
{
    int e = blockIdx.x * blockDim.x + threadIdx.x;
    if (e >= N_EDGES) return;
    int d = ei[N_EDGES + e], s = ei[e];
    if (g_need1[d]) g_csr1[g_base1[d] + atomicAdd(&g_fc1[d], 1)] = s;
    if (g_need2[d]) g_csr2[g_base2[d] + atomicAdd(&g_fc2[d], 1)] = s;
}

// ---------------- 9: layer-1 scores over listS --------------------------------
__global__ __launch_bounds__(256)
void scores1_k(const float* __restrict__ uT, const float* __restrict__ iT)
{
    int i    = (blockIdx.x * blockDim.x + threadIdx.x) >> 5;
    int lane = threadIdx.x & 31;
    if (i >= g_cntS) return;
    int n = g_listS[i];
    const float* xr = xrow(n, uT, iT);
    float v0 = xr[lane];      float v1 = xr[lane + 32];
    float v2 = xr[lane + 64]; float v3 = xr[lane + 96];
    #pragma unroll
    for (int h = 0; h < 4; h++) {
        const float* ws = g_ws1 + h * DIM;
        const float* wd = g_wd1 + h * DIM;
        float s = v0 * ws[lane] + v1 * ws[lane + 32] + v2 * ws[lane + 64] + v3 * ws[lane + 96];
        float d = v0 * wd[lane] + v1 * wd[lane + 32] + v2 * wd[lane + 64] + v3 * wd[lane + 96];
        s = wsum(s); d = wsum(d);
        if (lane == 0) { g_a1[n * 4 + h] = s; g_b1[n * 4 + h] = d; }
    }
}

// ---------------- 10: layer-1 gather (self + CSR edges, normalized) ----------
__global__ __launch_bounds__(256)
void gather1_k(const float* __restrict__ uT, const float* __restrict__ iT,
               const int* __restrict__ ei)
{
    int i    = (blockIdx.x * blockDim.x + threadIdx.x) >> 5;
    int lane = threadIdx.x & 31;
    if (i >= g_cnt1) return;
    int d = g_list1[i];
    float b1d0 = g_b1[d * 4 + 0], b1d1 = g_b1[d * 4 + 1];
    float b1d2 = g_b1[d * 4 + 2], b1d3 = g_b1[d * 4 + 3];
    // self loop
    float w0 = expf(lrelu(g_a1[d * 4 + 0] + b1d0));
    float w1 = expf(lrelu(g_a1[d * 4 + 1] + b1d1));
    float w2 = expf(lrelu(g_a1[d * 4 + 2] + b1d2));
    float w3 = expf(lrelu(g_a1[d * 4 + 3] + b1d3));
    float den0 = w0, den1 = w1, den2 = w2, den3 = w3;
    const float* xd = xrow(d, uT, iT);
    float sv0 = xd[lane];      float sv1 = xd[lane + 32];
    float sv2 = xd[lane + 64]; float sv3 = xd[lane + 96];
    float acc[4][4] = {
        {w0 * sv0, w0 * sv1, w0 * sv2, w0 * sv3},
        {w1 * sv0, w1 * sv1, w1 * sv2, w1 * sv3},
        {w2 * sv0, w2 * sv1, w2 * sv2, w2 * sv3},
        {w3 * sv0, w3 * sv1, w3 * sv2, w3 * sv3}};
    int base = g_base1[d], deg = g_deg1[d];
    for (int k = base; k < base + deg; k++) {
        int s = g_csr1[k];
        const float* xs = xrow(s, uT, iT);
        float e0 = xs[lane];      float e1 = xs[lane + 32];
        float e2 = xs[lane + 64]; float e3 = xs[lane + 96];
        float q0 = expf(lrelu(g_a1[s * 4 + 0] + b1d0));
        float q1 = expf(lrelu(g_a1[s * 4 + 1] + b1d1));
        float q2 = expf(lrelu(g_a1[s * 4 + 2] + b1d2));
        float q3 = expf(lrelu(g_a1[s * 4 + 3] + b1d3));
        den0 += q0; den1 += q1; den2 += q2; den3 += q3;
        acc[0][0] += q0 * e0; acc[0][1] += q0 * e1; acc[0][2] += q0 * e2; acc[0][3] += q0 * e3;
        acc[1][0] += q1 * e0; acc[1][1] += q1 * e1; acc[1][2] += q1 * e2; acc[1][3] += q1 * e3;
        acc[2][0] += q2 * e0; acc[2][1] += q2 * e1; acc[2][2] += q2 * e2; acc[2][3] += q2 * e3;
        acc[3][0] += q3 * e0; acc[3][1] += q3 * e1; acc[3][2] += q3 * e2; acc[3][3] += q3 * e3;
    }
    float i0 = 1.f / (den0 + 1e-16f), i1 = 1.f / (den1 + 1e-16f);
    float i2 = 1.f / (den2 + 1e-16f), i3 = 1.f / (den3 + 1e-16f);
    float* o0 = g_big + ((size_t)(d * 4 + 0)) * DIM;
    float* o1 = g_big + ((size_t)(d * 4 + 1)) * DIM;
    float* o2 = g_big + ((size_t)(d * 4 + 2)) * DIM;
    float* o3 = g_big + ((size_t)(d * 4 + 3)) * DIM;
    o0[lane] = acc[0][0] * i0; o0[lane + 32] = acc[0][1] * i0;
    o0[lane + 64] = acc[0][2] * i0; o0[lane + 96] = acc[0][3] * i0;
    o1[lane] = acc[1][0] * i1; o1[lane + 32] = acc[1][1] * i1;
    o1[lane + 64] = acc[1][2] * i1; o1[lane + 96] = acc[1][3] * i1;
    o2[lane] = acc[2][0] * i2; o2[lane + 32] = acc[2][1] * i2;
    o2[lane + 64] = acc[2][2] * i2; o2[lane + 96] = acc[2][3] * i2;
    o3[lane] = acc[3][0] * i3; o3[lane + 32] = acc[3][1] * i3;
    o3[lane + 64] = acc[3][2] * i3; o3[lane + 96] = acc[3][3] * i3;
}

// ---------------- 11: GEMM-1: h1 = elu(aggH @ W1blk + bias) ------------------
__global__ __launch_bounds__(256)
void gemm1_k(const float* __restrict__ W1, const float* __restrict__ bias1)
{
    __shared__ float As[32][132];
    __shared__ float Bs[32][36];
    __shared__ int   sNode[128];

    const int cnt  = g_cnt1;
    const int row0 = blockIdx.x * 128;
    if (row0 >= cnt) return;
    const int h   = blockIdx.y;
    const int tid = threadIdx.x;
    const int tx  = tid & 7;
    const int ty  = tid >> 3;

    if (tid < 128) {
        int r = row0 + tid;
        sNode[tid] = (r < cnt) ? g_list1[r] : g_list1[0];
    }
    __syncthreads();

    float acc[4][4];
    #pragma unroll
    for (int i = 0; i < 4; i++)
        #pragma unroll
        for (int j = 0; j < 4; j++) acc[i][j] = 0.f;

    const int lr = tid & 127;
    const int lq = (tid >> 7) * 16;
    const int bkr = tid >> 3;
    const int bbc = (tid & 7) * 4;

    for (int kk = 0; kk < DIM; kk += 32) {
        const bool valid = (row0 + lr < cnt);
        const float* ap = g_big + ((size_t)(sNode[lr] * 4 + h)) * DIM + kk + lq;
        #pragma unroll
        for (int q = 0; q < 4; q++) {
            float4 v = valid ? *(const float4*)(ap + q * 4)
                             : make_float4(0.f, 0.f, 0.f, 0.f);
            As[lq + q * 4 + 0][lr] = v.x;
            As[lq + q * 4 + 1][lr] = v.y;
            As[lq + q * 4 + 2][lr] = v.z;
            As[lq + q * 4 + 3][lr] = v.w;
        }
        *(float4*)&Bs[bkr][bbc] =
            *(const float4*)(W1 + (size_t)(kk + bkr) * DIM + h * 32 + bbc);
        __syncthreads();

        #pragma unroll
        for (int k = 0; k < 32; k++) {
            float4 a4 = *(const float4*)&As[k][ty * 4];
            float4 b4 = *(const float4*)&Bs[k][tx * 4];
            float a[4] = {a4.x, a4.y, a4.z, a4.w};
            float b[4] = {b4.x, b4.y, b4.z, b4.w};
            #pragma unroll
            for (int i = 0; i < 4; i++)
                #pragma unroll
                for (int j = 0; j < 4; j++)
                    acc[i][j] = fmaf(a[i], b[j], acc[i][j]);
        }
        __syncthreads();
    }

    const int colb = h * 32 + tx * 4;
    float b0 = bias1[colb], b1 = bias1[colb + 1], b2 = bias1[colb + 2], b3 = bias1[colb + 3];
    #pragma unroll
    for (int i = 0; i < 4; i++) {
        int row = ty * 4 + i;
        if (row0 + row < cnt) {
            float* o = g_h1 + (size_t)sNode[row] * DIM + colb;
            *(float4*)o = make_float4(
                eluf(acc[i][0] + b0), eluf(acc[i][1] + b1),
                eluf(acc[i][2] + b2), eluf(acc[i][3] + b3));
        }
    }
}

// ---------------- 12: layer-2 scores over list1 -------------------------------
__global__ __launch_bounds__(256)
void scores2_k()
{
    int i    = (blockIdx.x * blockDim.x + threadIdx.x) >> 5;
    int lane = threadIdx.x & 31;
    if (i >= g_cnt1) return;
    int n = g_list1[i];
    const float* hr = g_h1 + (size_t)n * DIM;
    float v0 = hr[lane];      float v1 = hr[lane + 32];
    float v2 = hr[lane + 64]; float v3 = hr[lane + 96];
    float s = v0 * g_ws2[lane] + v1 * g_ws2[lane + 32]
            + v2 * g_ws2[lane + 64] + v3 * g_ws2[lane + 96];
    float t = v0 * g_wd2[lane] + v1 * g_wd2[lane + 32]
            + v2 * g_wd2[lane + 64] + v3 * g_wd2[lane + 96];
    s = wsum(s); t = wsum(t);
    if (lane == 0) { g_a2[n] = s; g_b2[n] = t; }
}

// ---------------- 13: layer-2 gather (self + CSR edges, normalized) ----------
__global__ __launch_bounds__(256)
void gather2_k()
{
    int i    = (blockIdx.x * blockDim.x + threadIdx.x) >> 5;
    int lane = threadIdx.x & 31;
    if (i >= g_cnt2) return;
    int d = g_list2[i];
    float b2d = g_b2[d];
    float w = expf(lrelu(g_a2[d] + b2d));
    float den = w;
    const float* hd = g_h1 + (size_t)d * DIM;
    float a0 = w * hd[lane];      float a1 = w * hd[lane + 32];
    float a2 = w * hd[lane + 64]; float a3 = w * hd[lane + 96];
    int base = g_base2[d], deg = g_deg2[d];
    for (int k = base; k < base + deg; k++) {
        int s = g_csr2[k];
        const float* hs = g_h1 + (size_t)s * DIM;
        float q = expf(lrelu(g_a2[s] + b2d));
        den += q;
        a0 += q * hs[lane];      a1 += q * hs[lane + 32];
        a2 += q * hs[lane + 64]; a3 += q * hs[lane + 96];
    }
    float inv = 1.f / (den + 1e-16f);
    float* o = g_big + (size_t)d * DIM;
    o[lane]      = a0 * inv;  o[lane + 32] = a1 * inv;
    o[lane + 64] = a2 * inv;  o[lane + 96] = a3 * inv;
}

// ---------------- 14: GEMM-2: h2 = elu(agg2 @ W2 + bias2) --------------------
__global__ __launch_bounds__(256)
void gemm2_k(const float* __restrict__ W2, const float* __restrict__ bias2)
{
    __shared__ float As[16][132];
    __shared__ float Bs[16][128];
    __shared__ int   sNode[128];

    const int cnt  = g_cnt2;
    const int row0 = blockIdx.x * 128;
    if (row0 >= cnt) return;
    const int tid = threadIdx.x;
    const int tx  = tid & 15;
    const int ty  = tid >> 4;

    if (tid < 128) {
        int r = row0 + tid;
        sNode[tid] = (r < cnt) ? g_list2[r] : g_list2[0];
    }
    __syncthreads();

    float acc[8][8];
    #pragma unroll
    for (int i = 0; i < 8; i++)
        #pragma unroll
        for (int j = 0; j < 8; j++) acc[i][j] = 0.f;

    const int lr = tid & 127;
    const int lq = (tid >> 7) * 8;
    const int bkr = tid >> 4;
    const int bbc = (tid & 15) * 8;

    for (int kk = 0; kk < DIM; kk += 16) {
        const bool valid = (row0 + lr < cnt);
        const float* ap = g_big + (size_t)sNode[lr] * DIM + kk + lq;
        #pragma unroll
        for (int q = 0; q < 2; q++) {
            float4 v = valid ? *(const float4*)(ap + q * 4)
                             : make_float4(0.f, 0.f, 0.f, 0.f);
            As[lq + q * 4 + 0][lr] = v.x;
            As[lq + q * 4 + 1][lr] = v.y;
            As[lq + q * 4 + 2][lr] = v.z;
            As[lq + q * 4 + 3][lr] = v.w;
        }
        *(float4*)&Bs[bkr][bbc]     = *(const float4*)(W2 + (size_t)(kk + bkr) * DIM + bbc);
        *(float4*)&Bs[bkr][bbc + 4] = *(const float4*)(W2 + (size_t)(kk + bkr) * DIM + bbc + 4);
        __syncthreads();

        #pragma unroll
        for (int k = 0; k < 16; k++) {
            float4 a0 = *(const float4*)&As[k][ty * 8];
            float4 a1 = *(const float4*)&As[k][ty * 8 + 4];
            float4 b0 = *(const float4*)&Bs[k][tx * 8];
            float4 b1 = *(const float4*)&Bs[k][tx * 8 + 4];
            float a[8] = {a0.x, a0.y, a0.z, a0.w, a1.x, a1.y, a1.z, a1.w};
            float b[8] = {b0.x, b0.y, b0.z, b0.w, b1.x, b1.y, b1.z, b1.w};
            #pragma unroll
            for (int i = 0; i < 8; i++)
                #pragma unroll
                for (int j = 0; j < 8; j++)
                    acc[i][j] = fmaf(a[i], b[j], acc[i][j]);
        }
        __syncthreads();
    }

    const int colb = tx * 8;
    float bb[8];
    #pragma unroll
    for (int j = 0; j < 8; j++) bb[j] = bias2[colb + j];
    #pragma unroll
    for (int i = 0; i < 8; i++) {
        int row = ty * 8 + i;
        if (row0 + row < cnt) {
            float* o = g_h1 + (size_t)sNode[row] * DIM + colb;   // h2 aliases h1
            *(float4*)(o) = make_float4(
                eluf(acc[i][0] + bb[0]), eluf(acc[i][1] + bb[1]),
                eluf(acc[i][2] + bb[2]), eluf(acc[i][3] + bb[3]));
            *(float4*)(o + 4) = make_float4(
                eluf(acc[i][4] + bb[4]), eluf(acc[i][5] + bb[5]),
                eluf(acc[i][6] + bb[6]), eluf(acc[i][7] + bb[7]));
        }
    }
}

// ---------------- 15: final dot + sigmoid ------------------------------------
__global__ __launch_bounds__(256)
void final_k(const int* __restrict__ uidx, const int* __restrict__ iidx,
             float* __restrict__ res)
{
    int b    = (blockIdx.x * blockDim.x + threadIdx.x) >> 5;
    int lane = threadIdx.x & 31;
    if (b >= BATCH) return;
    const float* ru = g_h1 + (size_t)uidx[b] * DIM;
    const float* rv = g_h1 + (size_t)(iidx[b] + NUM_USERS) * DIM;
    float dot = ru[lane]      * rv[lane]
              + ru[lane + 32] * rv[lane + 32]
              + ru[lane + 64] * rv[lane + 64]
              + ru[lane + 96] * rv[lane + 96];
    dot = wsum(dot);
    if (lane == 0) res[b] = 1.f / (1.f + expf(-dot));
}

// ---------------- launch -----------------------------------------------------
extern "C" void kernel_launch(void* const* d_in, const int* in_sizes, int n_in,
                              void* d_out, int out_size)
{
    const int*   uidx  = (const int*)  d_in[0];
    const int*   iidx  = (const int*)  d_in[1];
    const int*   ei    = (const int*)  d_in[2];
    const float* userT = (const float*)d_in[3];
    const float* itemT = (const float*)d_in[4];
    const float* W1    = (const float*)d_in[5];
    const float* attS1 = (const float*)d_in[6];
    const float* attD1 = (const float*)d_in[7];
    const float* bias1 = (const float*)d_in[8];
    const float* W2    = (const float*)d_in[9];
    const float* attS2 = (const float*)d_in[10];
    const float* attD2 = (const float*)d_in[11];
    const float* bias2 = (const float*)d_in[12];
    float* res = (float*)d_out;

    const int nodeB = (N_NODES + 255) / 256;
    const int edgeB = (N_EDGES + 255) / 256;

    prep_k   <<<1, 128>>>(W1, attS1, attD1, W2, attS2, attD2);
    zero_k   <<<nodeB, 256>>>();
    mark2_k  <<<(BATCH + 255) / 256, 256>>>(uidx, iidx);
    mark1_k  <<<edgeB, 256>>>(ei);
    markC_k  <<<edgeB, 256>>>(ei);
    compact_k<<<nodeB, 256>>>();
    alloc_k  <<<(MAXL1 + 255) / 256, 256>>>();
    fill_k   <<<edgeB, 256>>>(ei);

    scores1_k<<<(N_NODES + 7) / 8, 256>>>(userT, itemT);
    gather1_k<<<(MAXL1 + 7) / 8, 256>>>(userT, itemT, ei);
    gemm1_k  <<<dim3((MAXL1 + 127) / 128, 4), 256>>>(W1, bias1);

    scores2_k<<<(MAXL1 + 7) / 8, 256>>>();
    gather2_k<<<(MAXL2 + 7) / 8, 256>>>();
    gemm2_k  <<<(MAXL2 + 127) / 128, 256>>>(W2, bias2);

    final_k  <<<(BATCH + 7) / 8, 256>>>(uidx, iidx, res);
}

// round 9
// speedup vs baseline: 3.4616x; 1.1698x over previous
#include <cuda_runtime.h>
#include <math.h>
#include <stdint.h>

#define NUM_USERS 162541
#define NUM_ITEMS 59047
#define N_NODES   221588
#define DIM       128
#define N_EDGES   100000
#define BATCH     16384
#define MAXL1     132768    // |need1| <= 32768 + 100000
#define MAXL2     32768     // |need2| <= 32768

// ---------------- scratch (device globals; device-code use ONLY) ------------
// Invariant: masks/degrees/counters are ZERO on entry to every kernel_launch
// call (zero-init at load; each call cleans exactly what it dirtied).
__device__ float g_big[(size_t)N_NODES * 512];   // L1: aggH[n][h][128]; L2: agg2[n][128]
__device__ float g_h1 [(size_t)N_NODES * DIM];   // h1; later h2
__device__ unsigned char g_need1[N_NODES], g_need2[N_NODES];
__device__ int g_list1[MAXL1], g_list2[MAXL2];
__device__ int g_cnt1, g_cnt2, g_tot1, g_tot2;
__device__ int g_deg1[N_NODES], g_deg2[N_NODES];
__device__ int g_base1[N_NODES], g_base2[N_NODES];
__device__ int g_fc1[N_NODES], g_fc2[N_NODES];
__device__ int g_csr1[N_EDGES], g_csr2[N_EDGES];
__device__ float g_ws1[4 * DIM], g_wd1[4 * DIM];
__device__ float g_ws2[DIM],     g_wd2[DIM];

// ---------------- helpers ---------------------------------------------------
__device__ __forceinline__ float eluf(float x)  { return x > 0.f ? x : expm1f(x); }
__device__ __forceinline__ float lrelu(float x) { return x > 0.f ? x : 0.2f * x; }
__device__ __forceinline__ float wsum(float v) {
    #pragma unroll
    for (int o = 16; o; o >>= 1) v += __shfl_xor_sync(0xffffffffu, v, o);
    return v;
}
__device__ __forceinline__ const float* xrow(int n, const float* uT, const float* iT) {
    return (n < NUM_USERS) ? uT + (size_t)n * DIM
                           : iT + (size_t)(n - NUM_USERS) * DIM;
}

// ---------------- 1: prep (fold W@att, reset counters) + batch marks --------
__global__ __launch_bounds__(256)
void prep_k(const float* __restrict__ W1, const float* __restrict__ aS1,
            const float* __restrict__ aD1, const float* __restrict__ W2,
            const float* __restrict__ aS2, const float* __restrict__ aD2,
            const int* __restrict__ uidx, const int* __restrict__ iidx)
{
    if (blockIdx.x == 0) {
        int k = threadIdx.x;
        if (k == 255) { g_cnt1 = 0; g_cnt2 = 0; g_tot1 = 0; g_tot2 = 0; }
        if (k < 128) {
            #pragma unroll
            for (int h = 0; h < 4; h++) {
                float s = 0.f, d = 0.f;
                #pragma unroll
                for (int c = 0; c < 32; c++) {
                    float w = W1[k * DIM + h * 32 + c];
                    s = fmaf(w, aS1[h * 32 + c], s);
                    d = fmaf(w, aD1[h * 32 + c], d);
                }
                g_ws1[h * DIM + k] = s;
                g_wd1[h * DIM + k] = d;
            }
            float s2 = 0.f, d2 = 0.f;
            for (int j = 0; j < DIM; j++) {
                float w = W2[k * DIM + j];
                s2 = fmaf(w, aS2[j], s2);
                d2 = fmaf(w, aD2[j], d2);
            }
            g_ws2[k] = s2;
            g_wd2[k] = d2;
        }
    } else {
        int i = (blockIdx.x - 1) * 256 + threadIdx.x;
        if (i < BATCH) {
            int u = uidx[i], v = iidx[i] + NUM_USERS;
            g_need2[u] = 1; g_need1[u] = 1;
            g_need2[v] = 1; g_need1[v] = 1;
        }
    }
}

// ---------------- 2: need1 |= srcs of edges into need2 ----------------------
__global__ void mark1_k(const int* __restrict__ ei)
{
    int e = blockIdx.x * blockDim.x + threadIdx.x;
    if (e >= N_EDGES) return;
    if (g_need2[ei[N_EDGES + e]]) g_need1[ei[e]] = 1;
}

// ---------------- 3: degree histograms ---------------------------------------
__global__ void markC_k(const int* __restrict__ ei)
{
    int e = blockIdx.x * blockDim.x + threadIdx.x;
    if (e >= N_EDGES) return;
    int d = ei[N_EDGES + e];
    if (g_need1[d]) atomicAdd(&g_deg1[d], 1);
    if (g_need2[d]) atomicAdd(&g_deg2[d], 1);
}

// ---------------- 4: list compaction + CSR base allocation (fused) ----------
__global__ __launch_bounds__(256)
void compactalloc_k()
{
    __shared__ int w1[8], w2[8];
    __shared__ int base1, base2;
    int i = blockIdx.x * 256 + threadIdx.x;
    int w = threadIdx.x >> 5, lane = threadIdx.x & 31;
    bool in1 = (i < N_NODES) && g_need1[i];
    bool in2 = (i < N_NODES) && g_need2[i];
    unsigned m1 = __ballot_sync(~0u, in1);
    unsigned m2 = __ballot_sync(~0u, in2);
    if (lane == 0) { w1[w] = __popc(m1); w2[w] = __popc(m2); }
    __syncthreads();
    if (threadIdx.x == 0) {
        int t1 = 0, t2 = 0;
        #pragma unroll
        for (int k = 0; k < 8; k++) {
            int v1 = w1[k]; w1[k] = t1; t1 += v1;
            int v2 = w2[k]; w2[k] = t2; t2 += v2;
        }
        base1 = (t1 > 0) ? atomicAdd(&g_cnt1, t1) : 0;
        base2 = (t2 > 0) ? atomicAdd(&g_cnt2, t2) : 0;
    }
    __syncthreads();
    unsigned lm = (1u << lane) - 1u;
    if (in1) g_list1[base1 + w1[w] + __popc(m1 & lm)] = i;
    if (in2) g_list2[base2 + w2[w] + __popc(m2 & lm)] = i;
    // CSR base ranges: warp-aggregated prefix over degrees (order-free)
    {
        int deg = in1 ? g_deg1[i] : 0;
        int inc = deg;
        #pragma unroll
        for (int o = 1; o < 32; o <<= 1) {
            int t = __shfl_up_sync(~0u, inc, o);
            if (lane >= o) inc += t;
        }
        int tot = __shfl_sync(~0u, inc, 31);
        int wb = 0;
        if (lane == 31 && tot > 0) wb = atomicAdd(&g_tot1, tot);
        wb = __shfl_sync(~0u, wb, 31);
        if (in1) g_base1[i] = wb + inc - deg;
    }
    {
        int deg = in2 ? g_deg2[i] : 0;
        int inc = deg;
        #pragma unroll
        for (int o = 1; o < 32; o <<= 1) {
            int t = __shfl_up_sync(~0u, inc, o);
            if (lane >= o) inc += t;
        }
        int tot = __shfl_sync(~0u, inc, 31);
        int wb = 0;
        if (lane == 31 && tot > 0) wb = atomicAdd(&g_tot2, tot);
        wb = __shfl_sync(~0u, wb, 31);
        if (in2) g_base2[i] = wb + inc - deg;
    }
}

// ---------------- 5: CSR fill -------------------------------------------------
__global__ void fill_k(const int* __restrict__ ei)
{
    int e = blockIdx.x * blockDim.x + threadIdx.x;
    if (e >= N_EDGES) return;
    int d = ei[N_EDGES + e], s = ei[e];
    if (g_need1[d]) g_csr1[g_base1[d] + atomicAdd(&g_fc1[d], 1)] = s;
    if (g_need2[d]) g_csr2[g_base2[d] + atomicAdd(&g_fc2[d], 1)] = s;
}

// ---------------- 6: layer-1 gather with INLINE scores + cleanup -------------
__global__ __launch_bounds__(256)
void gather1_k(const float* __restrict__ uT, const float* __restrict__ iT)
{
    int i    = (blockIdx.x * blockDim.x + threadIdx.x) >> 5;
    int lane = threadIdx.x & 31;
    if (i >= g_cnt1) return;
    int d = g_list1[i];

    // stage folded attention weights (per-lane slices) in registers
    float wsr[4][4], wdr[4][4];
    #pragma unroll
    for (int h = 0; h < 4; h++)
        #pragma unroll
        for (int j = 0; j < 4; j++) {
            wsr[h][j] = g_ws1[h * DIM + lane + 32 * j];
            wdr[h][j] = g_wd1[h * DIM + lane + 32 * j];
        }

    const float* xd = xrow(d, uT, iT);
    float v[4] = {xd[lane], xd[lane + 32], xd[lane + 64], xd[lane + 96]};

    // dst scores (a_src[d] for self, a_dst[d] for all incoming)
    float bd[4], den[4];
    float acc[4][4];
    #pragma unroll
    for (int h = 0; h < 4; h++) {
        float ad = wsum(v[0] * wsr[h][0] + v[1] * wsr[h][1] +
                        v[2] * wsr[h][2] + v[3] * wsr[h][3]);
        bd[h]    = wsum(v[0] * wdr[h][0] + v[1] * wdr[h][1] +
                        v[2] * wdr[h][2] + v[3] * wdr[h][3]);
        float w = expf(lrelu(ad + bd[h]));
        den[h] = w;
        #pragma unroll
        for (int j = 0; j < 4; j++) acc[h][j] = w * v[j];
    }

    int base = g_base1[d], deg = g_deg1[d];
    for (int k = base; k < base + deg; k++) {
        int s = g_csr1[k];
        const float* xs = xrow(s, uT, iT);
        float e0 = xs[lane];      float e1 = xs[lane + 32];
        float e2 = xs[lane + 64]; float e3 = xs[lane + 96];
        #pragma unroll
        for (int h = 0; h < 4; h++) {
            float as = wsum(e0 * wsr[h][0] + e1 * wsr[h][1] +
                            e2 * wsr[h][2] + e3 * wsr[h][3]);
            float q = expf(lrelu(as + bd[h]));
            den[h] += q;
            acc[h][0] += q * e0; acc[h][1] += q * e1;
            acc[h][2] += q * e2; acc[h][3] += q * e3;
        }
    }

    #pragma unroll
    for (int h = 0; h < 4; h++) {
        float inv = 1.f / (den[h] + 1e-16f);
        float* o = g_big + ((size_t)(d * 4 + h)) * DIM;
        o[lane]      = acc[h][0] * inv;  o[lane + 32] = acc[h][1] * inv;
        o[lane + 64] = acc[h][2] * inv;  o[lane + 96] = acc[h][3] * inv;
    }
    if (lane == 0) { g_need1[d] = 0; g_deg1[d] = 0; g_fc1[d] = 0; }   // self-clean
}

// ---------------- 7: GEMM-1: h1 = elu(aggH @ W1blk + bias) -------------------
__global__ __launch_bounds__(256)
void gemm1_k(const float* __restrict__ W1, const float* __restrict__ bias1)
{
    __shared__ float As[32][132];
    __shared__ float Bs[32][36];
    __shared__ int   sNode[128];

    const int cnt  = g_cnt1;
    const int row0 = blockIdx.x * 128;
    if (row0 >= cnt) return;
    const int h   = blockIdx.y;
    const int tid = threadIdx.x;
    const int tx  = tid & 7;
    const int ty  = tid >> 3;

    if (tid < 128) {
        int r = row0 + tid;
        sNode[tid] = (r < cnt) ? g_list1[r] : g_list1[0];
    }
    __syncthreads();

    float acc[4][4];
    #pragma unroll
    for (int i = 0; i < 4; i++)
        #pragma unroll
        for (int j = 0; j < 4; j++) acc[i][j] = 0.f;

    const int lr = tid & 127;
    const int lq = (tid >> 7) * 16;
    const int bkr = tid >> 3;
    const int bbc = (tid & 7) * 4;

    for (int kk = 0; kk < DIM; kk += 32) {
        const bool valid = (row0 + lr < cnt);
        const float* ap = g_big + ((size_t)(sNode[lr] * 4 + h)) * DIM + kk + lq;
        #pragma unroll
        for (int q = 0; q < 4; q++) {
            float4 vv = valid ? *(const float4*)(ap + q * 4)
                              : make_float4(0.f, 0.f, 0.f, 0.f);
            As[lq + q * 4 + 0][lr] = vv.x;
            As[lq + q * 4 + 1][lr] = vv.y;
            As[lq + q * 4 + 2][lr] = vv.z;
            As[lq + q * 4 + 3][lr] = vv.w;
        }
        *(float4*)&Bs[bkr][bbc] =
            *(const float4*)(W1 + (size_t)(kk + bkr) * DIM + h * 32 + bbc);
        __syncthreads();

        #pragma unroll
        for (int k = 0; k < 32; k++) {
            float4 a4 = *(const float4*)&As[k][ty * 4];
            float4 b4 = *(const float4*)&Bs[k][tx * 4];
            float a[4] = {a4.x, a4.y, a4.z, a4.w};
            float b[4] = {b4.x, b4.y, b4.z, b4.w};
            #pragma unroll
            for (int i = 0; i < 4; i++)
                #pragma unroll
                for (int j = 0; j < 4; j++)
                    acc[i][j] = fmaf(a[i], b[j], acc[i][j]);
        }
        __syncthreads();
    }

    const int colb = h * 32 + tx * 4;
    float b0 = bias1[colb], b1 = bias1[colb + 1], b2 = bias1[colb + 2], b3 = bias1[colb + 3];
    #pragma unroll
    for (int i = 0; i < 4; i++) {
        int row = ty * 4 + i;
        if (row0 + row < cnt) {
            float* o = g_h1 + (size_t)sNode[row] * DIM + colb;
            *(float4*)o = make_float4(
                eluf(acc[i][0] + b0), eluf(acc[i][1] + b1),
                eluf(acc[i][2] + b2), eluf(acc[i][3] + b3));
        }
    }
}

// ---------------- 8: layer-2 gather with INLINE scores + cleanup -------------
__global__ __launch_bounds__(256)
void gather2_k()
{
    int i    = (blockIdx.x * blockDim.x + threadIdx.x) >> 5;
    int lane = threadIdx.x & 31;
    if (i >= g_cnt2) return;
    int d = g_list2[i];

    float wr[4], wdr[4];
    #pragma unroll
    for (int j = 0; j < 4; j++) {
        wr[j]  = g_ws2[lane + 32 * j];
        wdr[j] = g_wd2[lane + 32 * j];
    }

    const float* hd = g_h1 + (size_t)d * DIM;
    float v0 = hd[lane];      float v1 = hd[lane + 32];
    float v2 = hd[lane + 64]; float v3 = hd[lane + 96];
    float ad  = wsum(v0 * wr[0] + v1 * wr[1] + v2 * wr[2] + v3 * wr[3]);
    float b2d = wsum(v0 * wdr[0] + v1 * wdr[1] + v2 * wdr[2] + v3 * wdr[3]);
    float w = expf(lrelu(ad + b2d));
    float den = w;
    float a0 = w * v0, a1 = w * v1, a2 = w * v2, a3 = w * v3;

    int base = g_base2[d], deg = g_deg2[d];
    for (int k = base; k < base + deg; k++) {
        int s = g_csr2[k];
        const float* hs = g_h1 + (size_t)s * DIM;
        float e0 = hs[lane];      float e1 = hs[lane + 32];
        float e2 = hs[lane + 64]; float e3 = hs[lane + 96];
        float as = wsum(e0 * wr[0] + e1 * wr[1] + e2 * wr[2] + e3 * wr[3]);
        float q = expf(lrelu(as + b2d));
        den += q;
        a0 += q * e0; a1 += q * e1; a2 += q * e2; a3 += q * e3;
    }
    float inv = 1.f / (den + 1e-16f);
    float* o = g_big + (size_t)d * DIM;
    o[lane]      = a0 * inv;  o[lane + 32] = a1 * inv;
    o[lane + 64] = a2 * inv;  o[lane + 96] = a3 * inv;
    if (lane == 0) { g_need2[d] = 0; g_deg2[d] = 0; g_fc2[d] = 0; }   // self-clean
}

// ---------------- 9: GEMM-2: h2 = elu(agg2 @ W2 + bias2) ---------------------
__global__ __launch_bounds__(256)
void gemm2_k(const float* __restrict__ W2, const float* __restrict__ bias2)
{
    __shared__ float As[16][132];
    __shared__ float Bs[16][128];
    __shared__ int   sNode[128];

    const int cnt  = g_cnt2;
    const int row0 = blockIdx.x * 128;
    if (row0 >= cnt) return;
    const int tid = threadIdx.x;
    const int tx  = tid & 15;
    const int ty  = tid >> 4;

    if (tid < 128) {
        int r = row0 + tid;
        sNode[tid] = (r < cnt) ? g_list2[r] : g_list2[0];
    }
    __syncthreads();

    float acc[8][8];
    #pragma unroll
    for (int i = 0; i < 8; i++)
        #pragma unroll
        for (int j = 0; j < 8; j++) acc[i][j] = 0.f;

    const int lr = tid & 127;
    const int lq = (tid >> 7) * 8;
    const int bkr = tid >> 4;
    const int bbc = (tid & 15) * 8;

    for (int kk = 0; kk < DIM; kk += 16) {
        const bool valid = (row0 + lr < cnt);
        const float* ap = g_big + (size_t)sNode[lr] * DIM + kk + lq;
        #pragma unroll
        for (int q = 0; q < 2; q++) {
            float4 vv = valid ? *(const float4*)(ap + q * 4)
                              : make_float4(0.f, 0.f, 0.f, 0.f);
            As[lq + q * 4 + 0][lr] = vv.x;
            As[lq + q * 4 + 1][lr] = vv.y;
            As[lq + q * 4 + 2][lr] = vv.z;
            As[lq + q * 4 + 3][lr] = vv.w;
        }
        *(float4*)&Bs[bkr][bbc]     = *(const float4*)(W2 + (size_t)(kk + bkr) * DIM + bbc);
        *(float4*)&Bs[bkr][bbc + 4] = *(const float4*)(W2 + (size_t)(kk + bkr) * DIM + bbc + 4);
        __syncthreads();

        #pragma unroll
        for (int k = 0; k < 16; k++) {
            float4 a0 = *(const float4*)&As[k][ty * 8];
            float4 a1 = *(const float4*)&As[k][ty * 8 + 4];
            float4 b0 = *(const float4*)&Bs[k][tx * 8];
            float4 b1 = *(const float4*)&Bs[k][tx * 8 + 4];
            float a[8] = {a0.x, a0.y, a0.z, a0.w, a1.x, a1.y, a1.z, a1.w};
            float b[8] = {b0.x, b0.y, b0.z, b0.w, b1.x, b1.y, b1.z, b1.w};
            #pragma unroll
            for (int i = 0; i < 8; i++)
                #pragma unroll
                for (int j = 0; j < 8; j++)
                    acc[i][j] = fmaf(a[i], b[j], acc[i][j]);
        }
        __syncthreads();
    }

    const int colb = tx * 8;
    float bb[8];
    #pragma unroll
    for (int j = 0; j < 8; j++) bb[j] = bias2[colb + j];
    #pragma unroll
    for (int i = 0; i < 8; i++) {
        int row = ty * 8 + i;
        if (row0 + row < cnt) {
            float* o = g_h1 + (size_t)sNode[row] * DIM + colb;   // h2 aliases h1
            *(float4*)(o) = make_float4(
                eluf(acc[i][0] + bb[0]), eluf(acc[i][1] + bb[1]),
                eluf(acc[i][2] + bb[2]), eluf(acc[i][3] + bb[3]));
            *(float4*)(o + 4) = make_float4(
                eluf(acc[i][4] + bb[4]), eluf(acc[i][5] + bb[5]),
                eluf(acc[i][6] + bb[6]), eluf(acc[i][7] + bb[7]));
        }
    }
}

// ---------------- 10: final dot + sigmoid ------------------------------------
__global__ __launch_bounds__(256)
void final_k(const int* __restrict__ uidx, const int* __restrict__ iidx,
             float* __restrict__ res)
{
    int b    = (blockIdx.x * blockDim.x + threadIdx.x) >> 5;
    int lane = threadIdx.x & 31;
    if (b >= BATCH) return;
    const float* ru = g_h1 + (size_t)uidx[b] * DIM;
    const float* rv = g_h1 + (size_t)(iidx[b] + NUM_USERS) * DIM;
    float dot = ru[lane]      * rv[lane]
              + ru[lane + 32] * rv[lane + 32]
              + ru[lane + 64] * rv[lane + 64]
              + ru[lane + 96] * rv[lane + 96];
    dot = wsum(dot);
    if (lane == 0) res[b] = 1.f / (1.f + expf(-dot));
}

// ---------------- launch -----------------------------------------------------
extern "C" void kernel_launch(void* const* d_in, const int* in_sizes, int n_in,
                              void* d_out, int out_size)
{
    const int*   uidx  = (const int*)  d_in[0];
    const int*   iidx  = (const int*)  d_in[1];
    const int*   ei    = (const int*)  d_in[2];
    const float* userT = (const float*)d_in[3];
    const float* itemT = (const float*)d_in[4];
    const float* W1    = (const float*)d_in[5];
    const float* attS1 = (const float*)d_in[6];
    const float* attD1 = (const float*)d_in[7];
    const float* bias1 = (const float*)d_in[8];
    const float* W2    = (const float*)d_in[9];
    const float* attS2 = (const float*)d_in[10];
    const float* attD2 = (const float*)d_in[11];
    const float* bias2 = (const float*)d_in[12];
    float* res = (float*)d_out;

    const int nodeB = (N_NODES + 255) / 256;
    const int edgeB = (N_EDGES + 255) / 256;

    prep_k       <<<1 + (BATCH + 255) / 256, 256>>>(W1, attS1, attD1,
                                                    W2, attS2, attD2, uidx, iidx);
    mark1_k      <<<edgeB, 256>>>(ei);
    markC_k      <<<edgeB, 256>>>(ei);
    compactalloc_k<<<nodeB, 256>>>();
    fill_k       <<<edgeB, 256>>>(ei);

    gather1_k    <<<(MAXL1 + 7) / 8, 256>>>(userT, itemT);
    gemm1_k      <<<dim3((MAXL1 + 127) / 128, 4), 256>>>(W1, bias1);

    gather2_k    <<<(MAXL2 + 7) / 8, 256>>>();
    gemm2_k      <<<(MAXL2 + 127) / 128, 256>>>(W2, bias2);

    final_k      <<<(BATCH + 7) / 8, 256>>>(uidx, iidx, res);
}